// round 6
// baseline (speedup 1.0000x reference)
#include <cuda_runtime.h>
#include <cstdint>
#include <math.h>

// ---------------- problem constants ----------------
#define D_MODEL 1024
#define DFF_DIM 4096
#define NTOK    2048          // B*S = 2*1024
#define NHEAD   16
#define DH      64
#define NLAYER  3
#define NCHUNK  16            // chunks per sequence
#define CLEN    64            // tokens per chunk

// ---------------- scratch (no allocs allowed) ----------------
__device__ float g_cur[NTOK * D_MODEL];
__device__ float g_q  [NTOK * D_MODEL];
__device__ float g_k  [NTOK * D_MODEL];
__device__ float g_v  [NTOK * D_MODEL];
__device__ float g_qf [NTOK * D_MODEL];
__device__ float g_kf [NTOK * D_MODEL];
__device__ float g_h  [NTOK * D_MODEL];
__device__ float g_ffn[NTOK * DFF_DIM];
__device__ float g_S  [32 * NCHUNK * DH * DH];
__device__ float g_Z  [32 * NCHUNK * DH];

// ================= helpers =================
__device__ __forceinline__ uint32_t f2tf32(float f) {
    uint32_t u;
    asm("cvt.rna.tf32.f32 %0, %1;" : "=r"(u) : "f"(f));
    return u;
}
__device__ __forceinline__ void mma_tf32(float c[4], uint32_t a0, uint32_t a1,
                                         uint32_t a2, uint32_t a3,
                                         uint32_t b0, uint32_t b1) {
    asm volatile(
        "mma.sync.aligned.m16n8k8.row.col.f32.tf32.tf32.f32 "
        "{%0,%1,%2,%3}, {%4,%5,%6,%7}, {%8,%9}, {%0,%1,%2,%3};"
        : "+f"(c[0]), "+f"(c[1]), "+f"(c[2]), "+f"(c[3])
        : "r"(a0), "r"(a1), "r"(a2), "r"(a3), "r"(b0), "r"(b1));
}

// ================= TF32 tensor-core GEMM (unchanged from round 5) =================
#define BK      64
#define ASTRIDE 68
#define BSTRIDE 136
#define ABUF (128 * ASTRIDE)
#define BBUF (64 * BSTRIDE)
#define GEMM_SMEM ((2 * ABUF + 2 * BBUF) * 4)

__device__ __forceinline__ void ldg_half(
    const float* __restrict__ A, const float* __restrict__ B,
    int K, int N, int bm, int bn, int k0, int koff,
    int ar, int ac, int br, int bc, float4 pa[4], float4 pb[4])
{
    const float* Ap = A + (size_t)(bm + ar) * K + k0 + koff + ac;
    #pragma unroll
    for (int i = 0; i < 4; i++) pa[i] = *(const float4*)(Ap + i * 4);
    const float* Bp = B + (size_t)(k0 + koff + br) * N + bn + bc;
    #pragma unroll
    for (int i = 0; i < 4; i++) pb[i] = *(const float4*)(Bp + i * 4);
}
__device__ __forceinline__ void sts_half(
    float* Ad, float* Bd, int koff,
    int ar, int ac, int br, int bc, const float4 pa[4], const float4 pb[4])
{
    #pragma unroll
    for (int i = 0; i < 4; i++) {
        uint4 u;
        u.x = f2tf32(pa[i].x); u.y = f2tf32(pa[i].y);
        u.z = f2tf32(pa[i].z); u.w = f2tf32(pa[i].w);
        *(uint4*)(Ad + ar * ASTRIDE + koff + ac + i * 4) = u;
    }
    #pragma unroll
    for (int i = 0; i < 4; i++) {
        uint4 u;
        u.x = f2tf32(pb[i].x); u.y = f2tf32(pb[i].y);
        u.z = f2tf32(pb[i].z); u.w = f2tf32(pb[i].w);
        *(uint4*)(Bd + (koff + br) * BSTRIDE + bc + i * 4) = u;
    }
}

__global__ __launch_bounds__(256, 1) void mma_gemm(
    const float* __restrict__ A,
    const float* __restrict__ B0, const float* __restrict__ B1, const float* __restrict__ B2,
    const float* __restrict__ bias0, const float* __restrict__ bias1, const float* __restrict__ bias2,
    float* __restrict__ C0, float* __restrict__ C1, float* __restrict__ C2,
    int M, int N, int K, int do_relu)
{
    extern __shared__ float sm[];
    float* AsB = sm;
    float* BsB = sm + 2 * ABUF;

    const int z = blockIdx.z;
    const float* B    = (z == 0) ? B0 : (z == 1) ? B1 : B2;
    const float* bias = (z == 0) ? bias0 : (z == 1) ? bias1 : bias2;
    float* C          = (z == 0) ? C0 : (z == 1) ? C1 : C2;

    const int tid  = threadIdx.x;
    const int bm   = blockIdx.y * 128;
    const int bn   = blockIdx.x * 128;
    const int lane = tid & 31;
    const int warp = tid >> 5;
    const int g    = lane >> 2;
    const int t    = lane & 3;
    const int m0   = (warp & 1) * 64;
    const int n0   = (warp >> 1) * 32;

    float acc[4][4][4];
    #pragma unroll
    for (int i = 0; i < 4; i++)
        #pragma unroll
        for (int j = 0; j < 4; j++)
            #pragma unroll
            for (int e = 0; e < 4; e++) acc[i][j][e] = 0.f;

    const int ar = tid >> 1;
    const int ac = (tid & 1) * 16;
    const int br = tid >> 3;
    const int bc = (tid & 7) * 16;

    const int NC = K / BK;
    float4 pa[4], pb[4];

    ldg_half(A, B, K, N, bm, bn, 0, 0,  ar, ac, br, bc, pa, pb);
    sts_half(AsB, BsB, 0,  ar, ac, br, bc, pa, pb);
    ldg_half(A, B, K, N, bm, bn, 0, 32, ar, ac, br, bc, pa, pb);
    sts_half(AsB, BsB, 32, ar, ac, br, bc, pa, pb);
    __syncthreads();

    for (int c = 0; c < NC; c++) {
        const int buf = c & 1;
        const int nb  = buf ^ 1;
        const uint32_t* Au = (const uint32_t*)(AsB + buf * ABUF);
        const uint32_t* Bu = (const uint32_t*)(BsB + buf * BBUF);
        float* Ad = AsB + nb * ABUF;
        float* Bd = BsB + nb * BBUF;
        const bool more = (c + 1 < NC);

        if (more) ldg_half(A, B, K, N, bm, bn, (c + 1) * BK, 0, ar, ac, br, bc, pa, pb);

        #pragma unroll
        for (int ks = 0; ks < 4; ks++) {
            const int kk = ks * 8;
            uint32_t af[4][4];
            #pragma unroll
            for (int mf = 0; mf < 4; mf++) {
                const int r = m0 + mf * 16 + g;
                af[mf][0] = Au[r * ASTRIDE + kk + t];
                af[mf][1] = Au[(r + 8) * ASTRIDE + kk + t];
                af[mf][2] = Au[r * ASTRIDE + kk + t + 4];
                af[mf][3] = Au[(r + 8) * ASTRIDE + kk + t + 4];
            }
            #pragma unroll
            for (int nf = 0; nf < 4; nf++) {
                const int cn = n0 + nf * 8 + g;
                uint32_t b0 = Bu[(kk + t) * BSTRIDE + cn];
                uint32_t b1 = Bu[(kk + t + 4) * BSTRIDE + cn];
                #pragma unroll
                for (int mf = 0; mf < 4; mf++)
                    mma_tf32(acc[mf][nf], af[mf][0], af[mf][1], af[mf][2], af[mf][3], b0, b1);
            }
        }

        if (more) {
            sts_half(Ad, Bd, 0, ar, ac, br, bc, pa, pb);
            ldg_half(A, B, K, N, bm, bn, (c + 1) * BK, 32, ar, ac, br, bc, pa, pb);
        }

        #pragma unroll
        for (int ks = 4; ks < 8; ks++) {
            const int kk = ks * 8;
            uint32_t af[4][4];
            #pragma unroll
            for (int mf = 0; mf < 4; mf++) {
                const int r = m0 + mf * 16 + g;
                af[mf][0] = Au[r * ASTRIDE + kk + t];
                af[mf][1] = Au[(r + 8) * ASTRIDE + kk + t];
                af[mf][2] = Au[r * ASTRIDE + kk + t + 4];
                af[mf][3] = Au[(r + 8) * ASTRIDE + kk + t + 4];
            }
            #pragma unroll
            for (int nf = 0; nf < 4; nf++) {
                const int cn = n0 + nf * 8 + g;
                uint32_t b0 = Bu[(kk + t) * BSTRIDE + cn];
                uint32_t b1 = Bu[(kk + t + 4) * BSTRIDE + cn];
                #pragma unroll
                for (int mf = 0; mf < 4; mf++)
                    mma_tf32(acc[mf][nf], af[mf][0], af[mf][1], af[mf][2], af[mf][3], b0, b1);
            }
        }

        if (more) {
            sts_half(Ad, Bd, 32, ar, ac, br, bc, pa, pb);
            __syncthreads();
        }
    }

    #pragma unroll
    for (int mf = 0; mf < 4; mf++) {
        const int r0 = bm + m0 + mf * 16 + g;
        #pragma unroll
        for (int nf = 0; nf < 4; nf++) {
            const int col = bn + n0 + nf * 8 + 2 * t;
            const float b0 = bias[col], b1 = bias[col + 1];
            float2 o0, o1;
            o0.x = acc[mf][nf][0] + b0; o0.y = acc[mf][nf][1] + b1;
            o1.x = acc[mf][nf][2] + b0; o1.y = acc[mf][nf][3] + b1;
            if (do_relu) {
                o0.x = fmaxf(o0.x, 0.f); o0.y = fmaxf(o0.y, 0.f);
                o1.x = fmaxf(o1.x, 0.f); o1.y = fmaxf(o1.y, 0.f);
            }
            *(float2*)(C + (size_t)r0 * N + col)       = o0;
            *(float2*)(C + (size_t)(r0 + 8) * N + col) = o1;
        }
    }
}

// ---------------- copy ----------------
__global__ void copy_kernel(const float* __restrict__ src, float* __restrict__ dst, int n)
{
    int i = blockIdx.x * blockDim.x + threadIdx.x;
    if (i < n) dst[i] = src[i];
}

// ---------------- FAVOR feature map (fused q/k via blockIdx.y) ----------------
__global__ __launch_bounds__(256) void favor_kernel(
    const float* __restrict__ X0, const float* __restrict__ X1,
    const float* __restrict__ omega,
    float* __restrict__ P0, float* __restrict__ P1)
{
    __shared__ float om[DH * 32];
    __shared__ float xsb[8][DH];

    const float* X = blockIdx.y ? X1 : X0;
    float* Phi     = blockIdx.y ? P1 : P0;

    const int tid = threadIdx.x;
    for (int i = tid; i < DH * 32; i += 256) om[i] = omega[i];

    const int w    = tid >> 5;
    const int lane = tid & 31;
    const int gw   = blockIdx.x * 8 + w;
    const int token = gw >> 4;
    const int head  = gw & 15;

    const float scale = 0.35355339059327373f;   // 64^-0.25
    const size_t base = (size_t)token * D_MODEL + head * DH;

    float x0 = X[base + lane]      * scale;
    float x1 = X[base + 32 + lane] * scale;
    xsb[w][lane]      = x0;
    xsb[w][lane + 32] = x1;

    float hh = x0 * x0 + x1 * x1;
    #pragma unroll
    for (int o = 16; o; o >>= 1) hh += __shfl_xor_sync(0xffffffffu, hh, o);
    hh *= 0.5f;

    __syncthreads();

    float u = 0.f;
    #pragma unroll
    for (int d = 0; d < DH; d++)
        u = fmaf(xsb[w][d], om[d * 32 + lane], u);

    const float c = 0.125f;   // 64^-0.5
    Phi[base + lane]      = expf(u  - hh) * c;
    Phi[base + 32 + lane] = expf(-u - hh) * c;
}

// ============ chunked causal linear attention (token-parallel) ============
#define CST 68   // smem tile stride (words), 68 mod 32 = 4

// load a 64x64 tile (token-major) from head-block layout into smem [t][d], stride CST
__device__ __forceinline__ void load_tile(
    float* dst, const float* __restrict__ src, size_t gbase, int tid)
{
    const int t = tid >> 2;
    const int qo = (tid & 3) * 16;
    const float* p = src + gbase + (size_t)t * D_MODEL + qo;
    float* d = dst + t * CST + qo;
    #pragma unroll
    for (int i = 0; i < 4; i++)
        *(float4*)(d + i * 4) = *(const float4*)(p + i * 4);
}

// Phase 1: per-chunk sums  S_c[m][d] = sum_t k[t][m] v[t][d] ,  z_c[m] = sum_t k[t][m]
__global__ __launch_bounds__(256) void chunk_sums_kernel(
    const float* __restrict__ Kf, const float* __restrict__ V,
    float* __restrict__ gS, float* __restrict__ gZ)
{
    __shared__ float ks[64 * CST];
    __shared__ float vs[64 * CST];

    const int ch = blockIdx.x;
    const int bh = blockIdx.y;
    const int tid = threadIdx.x;
    const int b = bh >> 4, hd = bh & 15;
    const size_t gbase = (size_t)b * 1024 * D_MODEL + (size_t)(ch * CLEN) * D_MODEL + hd * DH;

    load_tile(ks, Kf, gbase, tid);
    load_tile(vs, V,  gbase, tid);
    __syncthreads();

    const int m  = tid >> 2;
    const int dg = (tid & 3) * 16;

    float acc[16];
    #pragma unroll
    for (int i = 0; i < 16; i++) acc[i] = 0.f;
    float zz = 0.f;

    #pragma unroll 4
    for (int t = 0; t < CLEN; t++) {
        const float kv = ks[t * CST + m];
        zz += kv;
        const float* vp = vs + t * CST + dg;
        #pragma unroll
        for (int i = 0; i < 4; i++) {
            float4 v4 = *(const float4*)(vp + i * 4);
            acc[i*4+0] = fmaf(kv, v4.x, acc[i*4+0]);
            acc[i*4+1] = fmaf(kv, v4.y, acc[i*4+1]);
            acc[i*4+2] = fmaf(kv, v4.z, acc[i*4+2]);
            acc[i*4+3] = fmaf(kv, v4.w, acc[i*4+3]);
        }
    }

    const size_t idx = (size_t)(bh * NCHUNK + ch);
    float* Sp = gS + idx * 64 * 64 + m * 64 + dg;
    #pragma unroll
    for (int i = 0; i < 4; i++)
        *(float4*)(Sp + i * 4) = make_float4(acc[i*4], acc[i*4+1], acc[i*4+2], acc[i*4+3]);
    if ((tid & 3) == 0) gZ[idx * 64 + m] = zz;
}

// Phase 2: exclusive prefix over chunks (in-place), per (b,h)
__global__ __launch_bounds__(64) void chunk_prefix_kernel(
    float* __restrict__ gS, float* __restrict__ gZ)
{
    const int bh = blockIdx.x;
    const int d  = threadIdx.x;

    float run[64];
    #pragma unroll
    for (int m = 0; m < 64; m++) run[m] = 0.f;
    float zrun = 0.f;

    for (int ch = 0; ch < NCHUNK; ch++) {
        const size_t idx = (size_t)(bh * NCHUNK + ch);
        float* Sp = gS + idx * 64 * 64;
        float tmp[64];
        #pragma unroll
        for (int m = 0; m < 64; m++) tmp[m] = Sp[m * 64 + d];
        #pragma unroll
        for (int m = 0; m < 64; m++) { Sp[m * 64 + d] = run[m]; run[m] += tmp[m]; }
        float zt = gZ[idx * 64 + d];
        gZ[idx * 64 + d] = zrun;
        zrun += zt;
    }
}

// Phase 3: token-parallel intra-chunk attention
// A = mask(Qc Kc^T); Out = (A Vc + Qc Sp) / (q.zp + rowsum(A) + eps)
__global__ __launch_bounds__(256) void chunk_attn_kernel(
    const float* __restrict__ Qf, const float* __restrict__ Kf,
    const float* __restrict__ V, const float* __restrict__ gS,
    const float* __restrict__ gZ, float* __restrict__ Out)
{
    extern __shared__ float smw[];
    float* qs = smw;                 // 64*CST
    float* ks = smw + 64 * CST;
    float* vs = smw + 2 * 64 * CST;
    float* Sp = smw + 3 * 64 * CST;  // prefix state [m][d]
    float* Am = smw + 4 * 64 * CST;  // masked A [i][j]
    float* zp = smw + 5 * 64 * CST;  // 64

    const int ch = blockIdx.x;
    const int bh = blockIdx.y;
    const int tid = threadIdx.x;
    const int b = bh >> 4, hd = bh & 15;
    const size_t gbase = (size_t)b * 1024 * D_MODEL + (size_t)(ch * CLEN) * D_MODEL + hd * DH;
    const size_t idx = (size_t)(bh * NCHUNK + ch);

    load_tile(qs, Qf, gbase, tid);
    load_tile(ks, Kf, gbase, tid);
    load_tile(vs, V,  gbase, tid);
    // load prefix state: thread (m, quarter) from gS row-major [m][d]
    {
        const int m = tid >> 2;
        const int qo = (tid & 3) * 16;
        const float* p = gS + idx * 64 * 64 + m * 64 + qo;
        float* dstp = Sp + m * CST + qo;
        #pragma unroll
        for (int i = 0; i < 4; i++)
            *(float4*)(dstp + i * 4) = *(const float4*)(p + i * 4);
    }
    if (tid < 64) zp[tid] = gZ[idx * 64 + tid];
    __syncthreads();

    const int i  = tid >> 2;          // token in chunk
    const int jg = (tid & 3) * 16;    // j / d group

    // ---- A[i][j] = q_i . k_j , masked to j<=i; rowsum partial ----
    float a[16];
    #pragma unroll
    for (int e = 0; e < 16; e++) a[e] = 0.f;
    for (int m = 0; m < DH; m++) {
        const float qv = qs[i * CST + m];
        const float* kp = ks + m;   // ks[j][m] = ks[j*CST+m]
        #pragma unroll
        for (int e = 0; e < 16; e++)
            a[e] = fmaf(qv, kp[(jg + e) * CST], a[e]);
    }
    float rs = 0.f;
    #pragma unroll
    for (int e = 0; e < 16; e++) {
        if (jg + e > i) a[e] = 0.f;
        rs += a[e];
    }
    // write masked A row chunk
    {
        float* Ap = Am + i * CST + jg;
        #pragma unroll
        for (int e = 0; e < 16; e += 4)
            *(float4*)(Ap + e) = make_float4(a[e], a[e+1], a[e+2], a[e+3]);
    }
    // quad reduction of rowsum (threads 4i..4i+3 in same warp)
    rs += __shfl_xor_sync(0xffffffffu, rs, 1);
    rs += __shfl_xor_sync(0xffffffffu, rs, 2);
    // q_i . z_prefix
    float qz = 0.f;
    #pragma unroll
    for (int m = 0; m < DH; m++)
        qz = fmaf(qs[i * CST + m], zp[m], qz);
    const float den = qz + rs + 1e-6f;
    __syncthreads();

    // ---- num[i][d] = sum_m q[i][m] Sp[m][d] + sum_j A[i][j] v[j][d] ----
    float acc[16];
    #pragma unroll
    for (int e = 0; e < 16; e++) acc[e] = 0.f;

    for (int m = 0; m < DH; m++) {
        const float qv = qs[i * CST + m];
        const float* sp = Sp + m * CST + jg;
        #pragma unroll
        for (int e = 0; e < 4; e++) {
            float4 s4 = *(const float4*)(sp + e * 4);
            acc[e*4+0] = fmaf(qv, s4.x, acc[e*4+0]);
            acc[e*4+1] = fmaf(qv, s4.y, acc[e*4+1]);
            acc[e*4+2] = fmaf(qv, s4.z, acc[e*4+2]);
            acc[e*4+3] = fmaf(qv, s4.w, acc[e*4+3]);
        }
    }
    for (int j = 0; j <= i; j++) {
        const float av = Am[i * CST + j];
        const float* vp = vs + j * CST + jg;
        #pragma unroll
        for (int e = 0; e < 4; e++) {
            float4 v4 = *(const float4*)(vp + e * 4);
            acc[e*4+0] = fmaf(av, v4.x, acc[e*4+0]);
            acc[e*4+1] = fmaf(av, v4.y, acc[e*4+1]);
            acc[e*4+2] = fmaf(av, v4.z, acc[e*4+2]);
            acc[e*4+3] = fmaf(av, v4.w, acc[e*4+3]);
        }
    }

    const float inv = 1.f / den;
    float* op = Out + gbase + (size_t)i * D_MODEL + jg;
    #pragma unroll
    for (int e = 0; e < 4; e++) {
        float4 o;
        o.x = acc[e*4+0] * inv; o.y = acc[e*4+1] * inv;
        o.z = acc[e*4+2] * inv; o.w = acc[e*4+3] * inv;
        *(float4*)(op + e * 4) = o;
    }
}
#define ATTN_SMEM ((5 * 64 * CST + 64) * 4)

// ---------------- LayerNorm(out = LN(a + r) * g + b) ----------------
__global__ __launch_bounds__(256) void ln_kernel(
    float* __restrict__ out, const float* __restrict__ a,
    const float* __restrict__ r, const float* __restrict__ gam,
    const float* __restrict__ bet)
{
    const int row = blockIdx.x;
    const int tid = threadIdx.x;
    const float* pa = a + (size_t)row * D_MODEL;
    const float* pr = r + (size_t)row * D_MODEL;

    float v[4];
    float s = 0.f, ss = 0.f;
    #pragma unroll
    for (int i = 0; i < 4; i++) {
        int idx = tid + i * 256;
        float t = pa[idx] + pr[idx];
        v[i] = t; s += t; ss = fmaf(t, t, ss);
    }

    __shared__ float red[18];
    #pragma unroll
    for (int o = 16; o; o >>= 1) {
        s  += __shfl_xor_sync(0xffffffffu, s,  o);
        ss += __shfl_xor_sync(0xffffffffu, ss, o);
    }
    const int w = tid >> 5, lane = tid & 31;
    __shared__ float rw[16];
    if (lane == 0) { rw[w] = s; rw[w + 8] = ss; }
    __syncthreads();
    if (tid == 0) {
        float S0 = 0.f, S1 = 0.f;
        #pragma unroll
        for (int i = 0; i < 8; i++) { S0 += rw[i]; S1 += rw[i + 8]; }
        red[16] = S0; red[17] = S1;
    }
    __syncthreads();

    const float mean = red[16] * (1.f / 1024.f);
    const float var  = red[17] * (1.f / 1024.f) - mean * mean;
    const float inv  = rsqrtf(var + 1e-5f);

    float* po = out + (size_t)row * D_MODEL;
    #pragma unroll
    for (int i = 0; i < 4; i++) {
        int idx = tid + i * 256;
        po[idx] = (v[i] - mean) * inv * gam[idx] + bet[idx];
    }
}

// ---------------- launch ----------------
extern "C" void kernel_launch(void* const* d_in, const int* in_sizes, int n_in,
                              void* d_out, int out_size)
{
    const float* x    = (const float*)d_in[0];
    const float* Wq   = (const float*)d_in[1];
    const float* bq   = (const float*)d_in[2];
    const float* Wk   = (const float*)d_in[3];
    const float* bk   = (const float*)d_in[4];
    const float* Wv   = (const float*)d_in[5];
    const float* bv   = (const float*)d_in[6];
    const float* Wo   = (const float*)d_in[7];
    const float* bo   = (const float*)d_in[8];
    const float* omg  = (const float*)d_in[9];
    const float* ln1g = (const float*)d_in[10];
    const float* ln1b = (const float*)d_in[11];
    const float* ln2g = (const float*)d_in[12];
    const float* ln2b = (const float*)d_in[13];
    const float* W1   = (const float*)d_in[14];
    const float* bf1  = (const float*)d_in[15];
    const float* W2   = (const float*)d_in[16];
    const float* bf2  = (const float*)d_in[17];
    float* out = (float*)d_out;

    float *cur, *q, *k, *v, *qf, *kf, *h, *ffn, *gS, *gZ;
    cudaGetSymbolAddress((void**)&cur, g_cur);
    cudaGetSymbolAddress((void**)&q,   g_q);
    cudaGetSymbolAddress((void**)&k,   g_k);
    cudaGetSymbolAddress((void**)&v,   g_v);
    cudaGetSymbolAddress((void**)&qf,  g_qf);
    cudaGetSymbolAddress((void**)&kf,  g_kf);
    cudaGetSymbolAddress((void**)&h,   g_h);
    cudaGetSymbolAddress((void**)&ffn, g_ffn);
    cudaGetSymbolAddress((void**)&gS,  g_S);
    cudaGetSymbolAddress((void**)&gZ,  g_Z);

    cudaFuncSetAttribute(mma_gemm, cudaFuncAttributeMaxDynamicSharedMemorySize, GEMM_SMEM);
    cudaFuncSetAttribute(chunk_attn_kernel, cudaFuncAttributeMaxDynamicSharedMemorySize, ATTN_SMEM);

    const int nElem = NTOK * D_MODEL;
    copy_kernel<<<(nElem + 255) / 256, 256>>>(x, cur, nElem);

    const dim3 gQKV(D_MODEL / 128, NTOK / 128, 3);
    const dim3 gD(D_MODEL / 128, NTOK / 128, 1);
    const dim3 gF(DFF_DIM / 128, NTOK / 128, 1);
    const dim3 gCh(NCHUNK, 32);
    const dim3 gFav(NTOK * NHEAD / 8, 2);

    for (int l = 0; l < NLAYER; l++) {
        const size_t wDD  = (size_t)l * D_MODEL * D_MODEL;
        const size_t wDF  = (size_t)l * D_MODEL * DFF_DIM;
        const size_t bD   = (size_t)l * D_MODEL;
        const size_t bF   = (size_t)l * DFF_DIM;
        const size_t oOff = (size_t)l * DH * 32;

        mma_gemm<<<gQKV, 256, GEMM_SMEM>>>(cur,
            Wq + wDD, Wk + wDD, Wv + wDD,
            bq + bD, bk + bD, bv + bD,
            q, k, v, NTOK, D_MODEL, D_MODEL, 0);

        favor_kernel<<<gFav, 256>>>(q, k, omg + oOff, qf, kf);

        chunk_sums_kernel<<<gCh, 256>>>(kf, v, gS, gZ);
        chunk_prefix_kernel<<<32, 64>>>(gS, gZ);
        chunk_attn_kernel<<<gCh, 256, ATTN_SMEM>>>(qf, kf, v, gS, gZ, q);  // attn -> q

        mma_gemm<<<gD, 256, GEMM_SMEM>>>(q,
            Wo + wDD, Wo + wDD, Wo + wDD,
            bo + bD, bo + bD, bo + bD,
            k, k, k, NTOK, D_MODEL, D_MODEL, 0);
        ln_kernel<<<NTOK, 256>>>(h, cur, k, ln1g + bD, ln1b + bD);

        mma_gemm<<<gF, 256, GEMM_SMEM>>>(h,
            W1 + wDF, W1 + wDF, W1 + wDF,
            bf1 + bF, bf1 + bF, bf1 + bF,
            ffn, ffn, ffn, NTOK, DFF_DIM, D_MODEL, 1);
        mma_gemm<<<gD, 256, GEMM_SMEM>>>(ffn,
            W2 + wDF, W2 + wDF, W2 + wDF,
            bf2 + bD, bf2 + bD, bf2 + bD,
            v, v, v, NTOK, D_MODEL, DFF_DIM, 0);

        float* dst = (l == NLAYER - 1) ? out : cur;
        ln_kernel<<<NTOK, 256>>>(dst, h, v, ln2g + bD, ln2b + bD);
    }
}

// round 7
// speedup vs baseline: 1.1600x; 1.1600x over previous
#include <cuda_runtime.h>
#include <cstdint>
#include <math.h>

// ---------------- problem constants ----------------
#define D_MODEL 1024
#define DFF_DIM 4096
#define NTOK    2048          // B*S = 2*1024
#define NHEAD   16
#define DH      64
#define NLAYER  3
#define NCHUNK  16            // chunks per sequence
#define CLEN    64            // tokens per chunk

// ---------------- scratch (no allocs allowed) ----------------
__device__ float g_cur[NTOK * D_MODEL];
__device__ float g_q  [NTOK * D_MODEL];
__device__ float g_k  [NTOK * D_MODEL];
__device__ float g_v  [NTOK * D_MODEL];
__device__ float g_qf [NTOK * D_MODEL];
__device__ float g_kf [NTOK * D_MODEL];
__device__ float g_h  [NTOK * D_MODEL];
__device__ float g_ffn[NTOK * DFF_DIM];
__device__ float g_S  [32 * NCHUNK * DH * DH];
__device__ float g_Z  [32 * NCHUNK * DH];

// ================= helpers =================
__device__ __forceinline__ uint32_t f2tf32(float f) {
    uint32_t u;
    asm("cvt.rna.tf32.f32 %0, %1;" : "=r"(u) : "f"(f));
    return u;
}
__device__ __forceinline__ void mma_tf32(float c[4], uint32_t a0, uint32_t a1,
                                         uint32_t a2, uint32_t a3,
                                         uint32_t b0, uint32_t b1) {
    asm volatile(
        "mma.sync.aligned.m16n8k8.row.col.f32.tf32.tf32.f32 "
        "{%0,%1,%2,%3}, {%4,%5,%6,%7}, {%8,%9}, {%0,%1,%2,%3};"
        : "+f"(c[0]), "+f"(c[1]), "+f"(c[2]), "+f"(c[3])
        : "r"(a0), "r"(a1), "r"(a2), "r"(a3), "r"(b0), "r"(b1));
}

// ================= TF32 tensor-core GEMM (proven, unchanged) =================
#define BK      64
#define ASTRIDE 68
#define BSTRIDE 136
#define ABUF (128 * ASTRIDE)
#define BBUF (64 * BSTRIDE)
#define GEMM_SMEM ((2 * ABUF + 2 * BBUF) * 4)

__device__ __forceinline__ void ldg_half(
    const float* __restrict__ A, const float* __restrict__ B,
    int K, int N, int bm, int bn, int k0, int koff,
    int ar, int ac, int br, int bc, float4 pa[4], float4 pb[4])
{
    const float* Ap = A + (size_t)(bm + ar) * K + k0 + koff + ac;
    #pragma unroll
    for (int i = 0; i < 4; i++) pa[i] = *(const float4*)(Ap + i * 4);
    const float* Bp = B + (size_t)(k0 + koff + br) * N + bn + bc;
    #pragma unroll
    for (int i = 0; i < 4; i++) pb[i] = *(const float4*)(Bp + i * 4);
}
__device__ __forceinline__ void sts_half(
    float* Ad, float* Bd, int koff,
    int ar, int ac, int br, int bc, const float4 pa[4], const float4 pb[4])
{
    #pragma unroll
    for (int i = 0; i < 4; i++) {
        uint4 u;
        u.x = f2tf32(pa[i].x); u.y = f2tf32(pa[i].y);
        u.z = f2tf32(pa[i].z); u.w = f2tf32(pa[i].w);
        *(uint4*)(Ad + ar * ASTRIDE + koff + ac + i * 4) = u;
    }
    #pragma unroll
    for (int i = 0; i < 4; i++) {
        uint4 u;
        u.x = f2tf32(pb[i].x); u.y = f2tf32(pb[i].y);
        u.z = f2tf32(pb[i].z); u.w = f2tf32(pb[i].w);
        *(uint4*)(Bd + (koff + br) * BSTRIDE + bc + i * 4) = u;
    }
}

__global__ __launch_bounds__(256, 1) void mma_gemm(
    const float* __restrict__ A,
    const float* __restrict__ B0, const float* __restrict__ B1, const float* __restrict__ B2,
    const float* __restrict__ bias0, const float* __restrict__ bias1, const float* __restrict__ bias2,
    float* __restrict__ C0, float* __restrict__ C1, float* __restrict__ C2,
    int M, int N, int K, int do_relu)
{
    extern __shared__ float sm[];
    float* AsB = sm;
    float* BsB = sm + 2 * ABUF;

    const int z = blockIdx.z;
    const float* B    = (z == 0) ? B0 : (z == 1) ? B1 : B2;
    const float* bias = (z == 0) ? bias0 : (z == 1) ? bias1 : bias2;
    float* C          = (z == 0) ? C0 : (z == 1) ? C1 : C2;

    const int tid  = threadIdx.x;
    const int bm   = blockIdx.y * 128;
    const int bn   = blockIdx.x * 128;
    const int lane = tid & 31;
    const int warp = tid >> 5;
    const int g    = lane >> 2;
    const int t    = lane & 3;
    const int m0   = (warp & 1) * 64;
    const int n0   = (warp >> 1) * 32;

    float acc[4][4][4];
    #pragma unroll
    for (int i = 0; i < 4; i++)
        #pragma unroll
        for (int j = 0; j < 4; j++)
            #pragma unroll
            for (int e = 0; e < 4; e++) acc[i][j][e] = 0.f;

    const int ar = tid >> 1;
    const int ac = (tid & 1) * 16;
    const int br = tid >> 3;
    const int bc = (tid & 7) * 16;

    const int NC = K / BK;
    float4 pa[4], pb[4];

    ldg_half(A, B, K, N, bm, bn, 0, 0,  ar, ac, br, bc, pa, pb);
    sts_half(AsB, BsB, 0,  ar, ac, br, bc, pa, pb);
    ldg_half(A, B, K, N, bm, bn, 0, 32, ar, ac, br, bc, pa, pb);
    sts_half(AsB, BsB, 32, ar, ac, br, bc, pa, pb);
    __syncthreads();

    for (int c = 0; c < NC; c++) {
        const int buf = c & 1;
        const int nb  = buf ^ 1;
        const uint32_t* Au = (const uint32_t*)(AsB + buf * ABUF);
        const uint32_t* Bu = (const uint32_t*)(BsB + buf * BBUF);
        float* Ad = AsB + nb * ABUF;
        float* Bd = BsB + nb * BBUF;
        const bool more = (c + 1 < NC);

        if (more) ldg_half(A, B, K, N, bm, bn, (c + 1) * BK, 0, ar, ac, br, bc, pa, pb);

        #pragma unroll
        for (int ks = 0; ks < 4; ks++) {
            const int kk = ks * 8;
            uint32_t af[4][4];
            #pragma unroll
            for (int mf = 0; mf < 4; mf++) {
                const int r = m0 + mf * 16 + g;
                af[mf][0] = Au[r * ASTRIDE + kk + t];
                af[mf][1] = Au[(r + 8) * ASTRIDE + kk + t];
                af[mf][2] = Au[r * ASTRIDE + kk + t + 4];
                af[mf][3] = Au[(r + 8) * ASTRIDE + kk + t + 4];
            }
            #pragma unroll
            for (int nf = 0; nf < 4; nf++) {
                const int cn = n0 + nf * 8 + g;
                uint32_t b0 = Bu[(kk + t) * BSTRIDE + cn];
                uint32_t b1 = Bu[(kk + t + 4) * BSTRIDE + cn];
                #pragma unroll
                for (int mf = 0; mf < 4; mf++)
                    mma_tf32(acc[mf][nf], af[mf][0], af[mf][1], af[mf][2], af[mf][3], b0, b1);
            }
        }

        if (more) {
            sts_half(Ad, Bd, 0, ar, ac, br, bc, pa, pb);
            ldg_half(A, B, K, N, bm, bn, (c + 1) * BK, 32, ar, ac, br, bc, pa, pb);
        }

        #pragma unroll
        for (int ks = 4; ks < 8; ks++) {
            const int kk = ks * 8;
            uint32_t af[4][4];
            #pragma unroll
            for (int mf = 0; mf < 4; mf++) {
                const int r = m0 + mf * 16 + g;
                af[mf][0] = Au[r * ASTRIDE + kk + t];
                af[mf][1] = Au[(r + 8) * ASTRIDE + kk + t];
                af[mf][2] = Au[r * ASTRIDE + kk + t + 4];
                af[mf][3] = Au[(r + 8) * ASTRIDE + kk + t + 4];
            }
            #pragma unroll
            for (int nf = 0; nf < 4; nf++) {
                const int cn = n0 + nf * 8 + g;
                uint32_t b0 = Bu[(kk + t) * BSTRIDE + cn];
                uint32_t b1 = Bu[(kk + t + 4) * BSTRIDE + cn];
                #pragma unroll
                for (int mf = 0; mf < 4; mf++)
                    mma_tf32(acc[mf][nf], af[mf][0], af[mf][1], af[mf][2], af[mf][3], b0, b1);
            }
        }

        if (more) {
            sts_half(Ad, Bd, 32, ar, ac, br, bc, pa, pb);
            __syncthreads();
        }
    }

    #pragma unroll
    for (int mf = 0; mf < 4; mf++) {
        const int r0 = bm + m0 + mf * 16 + g;
        #pragma unroll
        for (int nf = 0; nf < 4; nf++) {
            const int col = bn + n0 + nf * 8 + 2 * t;
            const float b0 = bias[col], b1 = bias[col + 1];
            float2 o0, o1;
            o0.x = acc[mf][nf][0] + b0; o0.y = acc[mf][nf][1] + b1;
            o1.x = acc[mf][nf][2] + b0; o1.y = acc[mf][nf][3] + b1;
            if (do_relu) {
                o0.x = fmaxf(o0.x, 0.f); o0.y = fmaxf(o0.y, 0.f);
                o1.x = fmaxf(o1.x, 0.f); o1.y = fmaxf(o1.y, 0.f);
            }
            *(float2*)(C + (size_t)r0 * N + col)       = o0;
            *(float2*)(C + (size_t)(r0 + 8) * N + col) = o1;
        }
    }
}

// ---------------- copy ----------------
__global__ void copy_kernel(const float* __restrict__ src, float* __restrict__ dst, int n)
{
    int i = blockIdx.x * blockDim.x + threadIdx.x;
    if (i < n) dst[i] = src[i];
}

// ---------------- FAVOR feature map (fused q/k via blockIdx.y) ----------------
__global__ __launch_bounds__(256) void favor_kernel(
    const float* __restrict__ X0, const float* __restrict__ X1,
    const float* __restrict__ omega,
    float* __restrict__ P0, float* __restrict__ P1)
{
    __shared__ float om[DH * 32];
    __shared__ float xsb[8][DH];

    const float* X = blockIdx.y ? X1 : X0;
    float* Phi     = blockIdx.y ? P1 : P0;

    const int tid = threadIdx.x;
    for (int i = tid; i < DH * 32; i += 256) om[i] = omega[i];

    const int w    = tid >> 5;
    const int lane = tid & 31;
    const int gw   = blockIdx.x * 8 + w;
    const int token = gw >> 4;
    const int head  = gw & 15;

    const float scale = 0.35355339059327373f;   // 64^-0.25
    const size_t base = (size_t)token * D_MODEL + head * DH;

    float x0 = X[base + lane]      * scale;
    float x1 = X[base + 32 + lane] * scale;
    xsb[w][lane]      = x0;
    xsb[w][lane + 32] = x1;

    float hh = x0 * x0 + x1 * x1;
    #pragma unroll
    for (int o = 16; o; o >>= 1) hh += __shfl_xor_sync(0xffffffffu, hh, o);
    hh *= 0.5f;

    __syncthreads();

    float u = 0.f;
    #pragma unroll
    for (int d = 0; d < DH; d++)
        u = fmaf(xsb[w][d], om[d * 32 + lane], u);

    const float c = 0.125f;   // 64^-0.5
    Phi[base + lane]      = expf(u  - hh) * c;
    Phi[base + 32 + lane] = expf(-u - hh) * c;
}

// ============ chunked causal linear attention (token-parallel, v2) ============
#define CST 68   // smem tile stride (words)

// load 64x64 tile token-major [t][d]
__device__ __forceinline__ void load_tile(
    float* dst, const float* __restrict__ src, size_t gbase, int tid)
{
    const int t = tid >> 2;
    const int qo = (tid & 3) * 16;
    const float* p = src + gbase + (size_t)t * D_MODEL + qo;
    float* d = dst + t * CST + qo;
    #pragma unroll
    for (int i = 0; i < 4; i++)
        *(float4*)(d + i * 4) = *(const float4*)(p + i * 4);
}

// Phase 1: S_c[m][d] = sum_t k[t][m] v[t][d] ; z_c[m] = sum_t k[t][m]
// 256 threads: thread = (m-group 16) x (d-group 16); 4m x 4d outputs each.
__global__ __launch_bounds__(256) void chunk_sums_kernel(
    const float* __restrict__ Kf, const float* __restrict__ V,
    float* __restrict__ gS, float* __restrict__ gZ)
{
    __shared__ float ks[64 * CST];
    __shared__ float vs[64 * CST];

    const int ch = blockIdx.x;
    const int bh = blockIdx.y;
    const int tid = threadIdx.x;
    const int b = bh >> 4, hd = bh & 15;
    const size_t gbase = (size_t)b * 1024 * D_MODEL + (size_t)(ch * CLEN) * D_MODEL + hd * DH;

    load_tile(ks, Kf, gbase, tid);
    load_tile(vs, V,  gbase, tid);
    __syncthreads();

    const int mg = (tid >> 4) * 4;
    const int dg = (tid & 15) * 4;

    float acc[4][4];
    float zz[4];
    #pragma unroll
    for (int e = 0; e < 4; e++) {
        zz[e] = 0.f;
        #pragma unroll
        for (int c = 0; c < 4; c++) acc[e][c] = 0.f;
    }

    #pragma unroll 4
    for (int t = 0; t < CLEN; t++) {
        float4 v4 = *(const float4*)(vs + t * CST + dg);
        #pragma unroll
        for (int e = 0; e < 4; e++) {
            const float kv = ks[t * CST + mg + e];
            zz[e] += kv;
            acc[e][0] = fmaf(kv, v4.x, acc[e][0]);
            acc[e][1] = fmaf(kv, v4.y, acc[e][1]);
            acc[e][2] = fmaf(kv, v4.z, acc[e][2]);
            acc[e][3] = fmaf(kv, v4.w, acc[e][3]);
        }
    }

    const size_t idx = (size_t)(bh * NCHUNK + ch);
    #pragma unroll
    for (int e = 0; e < 4; e++)
        *(float4*)(gS + idx * 4096 + (size_t)(mg + e) * 64 + dg) =
            make_float4(acc[e][0], acc[e][1], acc[e][2], acc[e][3]);
    if ((tid & 15) == 0) {
        #pragma unroll
        for (int e = 0; e < 4; e++) gZ[idx * 64 + mg + e] = zz[e];
    }
}

// Phase 2: exclusive prefix over chunks (in-place), per (b,h)
__global__ __launch_bounds__(64) void chunk_prefix_kernel(
    float* __restrict__ gS, float* __restrict__ gZ)
{
    const int bh = blockIdx.x;
    const int d  = threadIdx.x;

    float run[64];
    #pragma unroll
    for (int m = 0; m < 64; m++) run[m] = 0.f;
    float zrun = 0.f;

    for (int ch = 0; ch < NCHUNK; ch++) {
        const size_t idx = (size_t)(bh * NCHUNK + ch);
        float* Sp = gS + idx * 4096;
        float tmp[64];
        #pragma unroll
        for (int m = 0; m < 64; m++) tmp[m] = Sp[m * 64 + d];
        #pragma unroll
        for (int m = 0; m < 64; m++) { Sp[m * 64 + d] = run[m]; run[m] += tmp[m]; }
        float zt = gZ[idx * 64 + d];
        gZ[idx * 64 + d] = zrun;
        zrun += zt;
    }
}

// Phase 3: token-parallel intra-chunk attention.
// Thread = (i-group 16) x (j/d-group 16), 4x4 outputs per phase.
// A = mask(Qc Kc^T); Out = (Qc Sp + A Vc) / (q.zp + rowsum(A) + eps)
__global__ __launch_bounds__(256) void chunk_attn_kernel(
    const float* __restrict__ Qf, const float* __restrict__ Kf,
    const float* __restrict__ V, const float* __restrict__ gS,
    const float* __restrict__ gZ, float* __restrict__ Out)
{
    extern __shared__ float smw[];
    float* qs = smw;                 // [i][m]
    float* kt = smw + 64 * CST;      // [m][j]  (K transposed)
    float* vs = smw + 2 * 64 * CST;  // [j][d]
    float* Sp = smw + 3 * 64 * CST;  // [m][d]
    float* Am = smw + 4 * 64 * CST;  // [i][j]  masked A
    float* zp = smw + 5 * 64 * CST;  // [m]

    const int ch = blockIdx.x;
    const int bh = blockIdx.y;
    const int tid = threadIdx.x;
    const int b = bh >> 4, hd = bh & 15;
    const size_t gbase = (size_t)b * 1024 * D_MODEL + (size_t)(ch * CLEN) * D_MODEL + hd * DH;
    const size_t idx = (size_t)(bh * NCHUNK + ch);

    load_tile(qs, Qf, gbase, tid);
    load_tile(vs, V,  gbase, tid);
    // K transposed: coalesced global read, scattered smem store (one-time)
    {
        const int t = tid >> 2;
        const int qo = (tid & 3) * 16;
        const float* p = Kf + gbase + (size_t)t * D_MODEL + qo;
        #pragma unroll
        for (int i = 0; i < 16; i += 4) {
            float4 kv = *(const float4*)(p + i);
            kt[(qo + i + 0) * CST + t] = kv.x;
            kt[(qo + i + 1) * CST + t] = kv.y;
            kt[(qo + i + 2) * CST + t] = kv.z;
            kt[(qo + i + 3) * CST + t] = kv.w;
        }
    }
    // prefix state rows
    {
        const int m = tid >> 2;
        const int qo = (tid & 3) * 16;
        const float* p = gS + idx * 4096 + (size_t)m * 64 + qo;
        float* dp = Sp + m * CST + qo;
        #pragma unroll
        for (int i = 0; i < 4; i++)
            *(float4*)(dp + i * 4) = *(const float4*)(p + i * 4);
    }
    if (tid < 64) zp[tid] = gZ[idx * 64 + tid];
    __syncthreads();

    const int ig = (tid >> 4) * 4;    // token group base
    const int jg = (tid & 15) * 4;    // j (phase A) / d (phase B) group base

    // ---- phase A: A, rowsum, qz ----
    float a[4][4];
    float qz[4];
    #pragma unroll
    for (int e = 0; e < 4; e++) {
        qz[e] = 0.f;
        #pragma unroll
        for (int c = 0; c < 4; c++) a[e][c] = 0.f;
    }
    #pragma unroll 4
    for (int m = 0; m < DH; m++) {
        const float zv = zp[m];
        float4 k4 = *(const float4*)(kt + m * CST + jg);
        #pragma unroll
        for (int e = 0; e < 4; e++) {
            const float qv = qs[(ig + e) * CST + m];
            qz[e] = fmaf(qv, zv, qz[e]);
            a[e][0] = fmaf(qv, k4.x, a[e][0]);
            a[e][1] = fmaf(qv, k4.y, a[e][1]);
            a[e][2] = fmaf(qv, k4.z, a[e][2]);
            a[e][3] = fmaf(qv, k4.w, a[e][3]);
        }
    }
    float den[4];
    #pragma unroll
    for (int e = 0; e < 4; e++) {
        const int i = ig + e;
        #pragma unroll
        for (int c = 0; c < 4; c++)
            if (jg + c > i) a[e][c] = 0.f;
        float rs = a[e][0] + a[e][1] + a[e][2] + a[e][3];
        rs += __shfl_xor_sync(0xffffffffu, rs, 1);
        rs += __shfl_xor_sync(0xffffffffu, rs, 2);
        rs += __shfl_xor_sync(0xffffffffu, rs, 4);
        rs += __shfl_xor_sync(0xffffffffu, rs, 8);
        den[e] = qz[e] + rs + 1e-6f;
        *(float4*)(Am + i * CST + jg) = make_float4(a[e][0], a[e][1], a[e][2], a[e][3]);
    }
    __syncthreads();

    // ---- phase B: out = (Q Sp + A V) / den ----
    float acc[4][4];
    #pragma unroll
    for (int e = 0; e < 4; e++)
        #pragma unroll
        for (int c = 0; c < 4; c++) acc[e][c] = 0.f;

    #pragma unroll 4
    for (int m = 0; m < DH; m++) {
        float4 s4 = *(const float4*)(Sp + m * CST + jg);
        #pragma unroll
        for (int e = 0; e < 4; e++) {
            const float qv = qs[(ig + e) * CST + m];
            acc[e][0] = fmaf(qv, s4.x, acc[e][0]);
            acc[e][1] = fmaf(qv, s4.y, acc[e][1]);
            acc[e][2] = fmaf(qv, s4.z, acc[e][2]);
            acc[e][3] = fmaf(qv, s4.w, acc[e][3]);
        }
    }
    const int jmax = ig + 3;   // Am is zero above the diagonal, so this bound is safe
    for (int j = 0; j <= jmax; j++) {
        float4 v4 = *(const float4*)(vs + j * CST + jg);
        #pragma unroll
        for (int e = 0; e < 4; e++) {
            const float av = Am[(ig + e) * CST + j];
            acc[e][0] = fmaf(av, v4.x, acc[e][0]);
            acc[e][1] = fmaf(av, v4.y, acc[e][1]);
            acc[e][2] = fmaf(av, v4.z, acc[e][2]);
            acc[e][3] = fmaf(av, v4.w, acc[e][3]);
        }
    }

    #pragma unroll
    for (int e = 0; e < 4; e++) {
        const float inv = 1.f / den[e];
        float* op = Out + gbase + (size_t)(ig + e) * D_MODEL + jg;
        *(float4*)op = make_float4(acc[e][0] * inv, acc[e][1] * inv,
                                   acc[e][2] * inv, acc[e][3] * inv);
    }
}
#define ATTN_SMEM ((5 * 64 * CST + 64) * 4)

// ---------------- LayerNorm(out = LN(a + r) * g + b) ----------------
__global__ __launch_bounds__(256) void ln_kernel(
    float* __restrict__ out, const float* __restrict__ a,
    const float* __restrict__ r, const float* __restrict__ gam,
    const float* __restrict__ bet)
{
    const int row = blockIdx.x;
    const int tid = threadIdx.x;
    const float* pa = a + (size_t)row * D_MODEL;
    const float* pr = r + (size_t)row * D_MODEL;

    float v[4];
    float s = 0.f, ss = 0.f;
    #pragma unroll
    for (int i = 0; i < 4; i++) {
        int idx = tid + i * 256;
        float t = pa[idx] + pr[idx];
        v[i] = t; s += t; ss = fmaf(t, t, ss);
    }

    __shared__ float red[18];
    #pragma unroll
    for (int o = 16; o; o >>= 1) {
        s  += __shfl_xor_sync(0xffffffffu, s,  o);
        ss += __shfl_xor_sync(0xffffffffu, ss, o);
    }
    const int w = tid >> 5, lane = tid & 31;
    __shared__ float rw[16];
    if (lane == 0) { rw[w] = s; rw[w + 8] = ss; }
    __syncthreads();
    if (tid == 0) {
        float S0 = 0.f, S1 = 0.f;
        #pragma unroll
        for (int i = 0; i < 8; i++) { S0 += rw[i]; S1 += rw[i + 8]; }
        red[16] = S0; red[17] = S1;
    }
    __syncthreads();

    const float mean = red[16] * (1.f / 1024.f);
    const float var  = red[17] * (1.f / 1024.f) - mean * mean;
    const float inv  = rsqrtf(var + 1e-5f);

    float* po = out + (size_t)row * D_MODEL;
    #pragma unroll
    for (int i = 0; i < 4; i++) {
        int idx = tid + i * 256;
        po[idx] = (v[i] - mean) * inv * gam[idx] + bet[idx];
    }
}

// ---------------- launch ----------------
extern "C" void kernel_launch(void* const* d_in, const int* in_sizes, int n_in,
                              void* d_out, int out_size)
{
    const float* x    = (const float*)d_in[0];
    const float* Wq   = (const float*)d_in[1];
    const float* bq   = (const float*)d_in[2];
    const float* Wk   = (const float*)d_in[3];
    const float* bk   = (const float*)d_in[4];
    const float* Wv   = (const float*)d_in[5];
    const float* bv   = (const float*)d_in[6];
    const float* Wo   = (const float*)d_in[7];
    const float* bo   = (const float*)d_in[8];
    const float* omg  = (const float*)d_in[9];
    const float* ln1g = (const float*)d_in[10];
    const float* ln1b = (const float*)d_in[11];
    const float* ln2g = (const float*)d_in[12];
    const float* ln2b = (const float*)d_in[13];
    const float* W1   = (const float*)d_in[14];
    const float* bf1  = (const float*)d_in[15];
    const float* W2   = (const float*)d_in[16];
    const float* bf2  = (const float*)d_in[17];
    float* out = (float*)d_out;

    float *cur, *q, *k, *v, *qf, *kf, *h, *ffn, *gS, *gZ;
    cudaGetSymbolAddress((void**)&cur, g_cur);
    cudaGetSymbolAddress((void**)&q,   g_q);
    cudaGetSymbolAddress((void**)&k,   g_k);
    cudaGetSymbolAddress((void**)&v,   g_v);
    cudaGetSymbolAddress((void**)&qf,  g_qf);
    cudaGetSymbolAddress((void**)&kf,  g_kf);
    cudaGetSymbolAddress((void**)&h,   g_h);
    cudaGetSymbolAddress((void**)&ffn, g_ffn);
    cudaGetSymbolAddress((void**)&gS,  g_S);
    cudaGetSymbolAddress((void**)&gZ,  g_Z);

    cudaFuncSetAttribute(mma_gemm, cudaFuncAttributeMaxDynamicSharedMemorySize, GEMM_SMEM);
    cudaFuncSetAttribute(chunk_attn_kernel, cudaFuncAttributeMaxDynamicSharedMemorySize, ATTN_SMEM);

    const int nElem = NTOK * D_MODEL;
    copy_kernel<<<(nElem + 255) / 256, 256>>>(x, cur, nElem);

    const dim3 gQKV(D_MODEL / 128, NTOK / 128, 3);
    const dim3 gD(D_MODEL / 128, NTOK / 128, 1);
    const dim3 gF(DFF_DIM / 128, NTOK / 128, 1);
    const dim3 gCh(NCHUNK, 32);
    const dim3 gFav(NTOK * NHEAD / 8, 2);

    for (int l = 0; l < NLAYER; l++) {
        const size_t wDD  = (size_t)l * D_MODEL * D_MODEL;
        const size_t wDF  = (size_t)l * D_MODEL * DFF_DIM;
        const size_t bD   = (size_t)l * D_MODEL;
        const size_t bF   = (size_t)l * DFF_DIM;
        const size_t oOff = (size_t)l * DH * 32;

        mma_gemm<<<gQKV, 256, GEMM_SMEM>>>(cur,
            Wq + wDD, Wk + wDD, Wv + wDD,
            bq + bD, bk + bD, bv + bD,
            q, k, v, NTOK, D_MODEL, D_MODEL, 0);

        favor_kernel<<<gFav, 256>>>(q, k, omg + oOff, qf, kf);

        chunk_sums_kernel<<<gCh, 256>>>(kf, v, gS, gZ);
        chunk_prefix_kernel<<<32, 64>>>(gS, gZ);
        chunk_attn_kernel<<<gCh, 256, ATTN_SMEM>>>(qf, kf, v, gS, gZ, q);  // attn -> q

        mma_gemm<<<gD, 256, GEMM_SMEM>>>(q,
            Wo + wDD, Wo + wDD, Wo + wDD,
            bo + bD, bo + bD, bo + bD,
            k, k, k, NTOK, D_MODEL, D_MODEL, 0);
        ln_kernel<<<NTOK, 256>>>(h, cur, k, ln1g + bD, ln1b + bD);

        mma_gemm<<<gF, 256, GEMM_SMEM>>>(h,
            W1 + wDF, W1 + wDF, W1 + wDF,
            bf1 + bF, bf1 + bF, bf1 + bF,
            ffn, ffn, ffn, NTOK, DFF_DIM, D_MODEL, 1);
        mma_gemm<<<gD, 256, GEMM_SMEM>>>(ffn,
            W2 + wDF, W2 + wDF, W2 + wDF,
            bf2 + bD, bf2 + bD, bf2 + bD,
            v, v, v, NTOK, D_MODEL, DFF_DIM, 0);

        float* dst = (l == NLAYER - 1) ? out : cur;
        ln_kernel<<<NTOK, 256>>>(dst, h, v, ln2g + bD, ln2b + bD);
    }
}

// round 8
// speedup vs baseline: 1.2662x; 1.0916x over previous
#include <cuda_runtime.h>
#include <cstdint>
#include <math.h>

// ---------------- problem constants ----------------
#define D_MODEL 1024
#define DFF_DIM 4096
#define NTOK    2048          // B*S = 2*1024
#define NHEAD   16
#define DH      64
#define NLAYER  3
#define NCHUNK  16            // chunks per sequence
#define CLEN    64            // tokens per chunk

// ---------------- scratch (no allocs allowed) ----------------
__device__ float g_cur[NTOK * D_MODEL];
__device__ float g_q  [NTOK * D_MODEL];
__device__ float g_k  [NTOK * D_MODEL];
__device__ float g_v  [NTOK * D_MODEL];
__device__ float g_qf [NTOK * D_MODEL];
__device__ float g_kf [NTOK * D_MODEL];
__device__ float g_h  [NTOK * D_MODEL];
__device__ float g_ffn[NTOK * DFF_DIM];
__device__ float g_S  [32 * NCHUNK * DH * DH];
__device__ float g_Z  [32 * NCHUNK * DH];

// ================= helpers =================
__device__ __forceinline__ uint32_t f2tf32(float f) {
    uint32_t u;
    asm("cvt.rna.tf32.f32 %0, %1;" : "=r"(u) : "f"(f));
    return u;
}
__device__ __forceinline__ void mma_tf32(float c[4], uint32_t a0, uint32_t a1,
                                         uint32_t a2, uint32_t a3,
                                         uint32_t b0, uint32_t b1) {
    asm volatile(
        "mma.sync.aligned.m16n8k8.row.col.f32.tf32.tf32.f32 "
        "{%0,%1,%2,%3}, {%4,%5,%6,%7}, {%8,%9}, {%0,%1,%2,%3};"
        : "+f"(c[0]), "+f"(c[1]), "+f"(c[2]), "+f"(c[3])
        : "r"(a0), "r"(a1), "r"(a2), "r"(a3), "r"(b0), "r"(b1));
}

// ================= TF32 tensor-core GEMM =================
// B smem layout: row stride 168 words (== 8 mod 32, keeps frag reads
// conflict-free), with a 4-word pad after every 32 data words so the
// staging STS.128s are also conflict-free:
//   physical col = col + (col>>5)*4   (data span 140 <= 168)
#define BK      64
#define ASTRIDE 68
#define BSTRIDE 168
#define ABUF (128 * ASTRIDE)          // 8704 words
#define BBUF (64 * BSTRIDE)           // 10752 words
#define GEMM_SMEM ((2 * ABUF + 2 * BBUF) * 4)   // 155648 bytes

__device__ __forceinline__ void ldg_half(
    const float* __restrict__ A, const float* __restrict__ B,
    int K, int N, int bm, int bn, int k0, int koff,
    int ar, int ac, int br, int bc, float4 pa[4], float4 pb[4])
{
    const float* Ap = A + (size_t)(bm + ar) * K + k0 + koff + ac;
    #pragma unroll
    for (int i = 0; i < 4; i++) pa[i] = *(const float4*)(Ap + i * 4);
    const float* Bp = B + (size_t)(k0 + koff + br) * N + bn + bc;
    #pragma unroll
    for (int i = 0; i < 4; i++) pb[i] = *(const float4*)(Bp + i * 4);
}
__device__ __forceinline__ void sts_half(
    float* Ad, float* Bd, int koff,
    int ar, int ac, int br, int bc, const float4 pa[4], const float4 pb[4])
{
    #pragma unroll
    for (int i = 0; i < 4; i++) {
        uint4 u;
        u.x = f2tf32(pa[i].x); u.y = f2tf32(pa[i].y);
        u.z = f2tf32(pa[i].z); u.w = f2tf32(pa[i].w);
        *(uint4*)(Ad + ar * ASTRIDE + koff + ac + i * 4) = u;
    }
    const int bcp = bc + ((bc >> 5) << 2);   // padded column base (const per thread)
    #pragma unroll
    for (int i = 0; i < 4; i++) {
        uint4 u;
        u.x = f2tf32(pb[i].x); u.y = f2tf32(pb[i].y);
        u.z = f2tf32(pb[i].z); u.w = f2tf32(pb[i].w);
        *(uint4*)(Bd + (koff + br) * BSTRIDE + bcp + i * 4) = u;
    }
}

__global__ __launch_bounds__(256, 1) void mma_gemm(
    const float* __restrict__ A,
    const float* __restrict__ B0, const float* __restrict__ B1, const float* __restrict__ B2,
    const float* __restrict__ bias0, const float* __restrict__ bias1, const float* __restrict__ bias2,
    float* __restrict__ C0, float* __restrict__ C1, float* __restrict__ C2,
    int M, int N, int K, int do_relu)
{
    extern __shared__ float sm[];
    float* AsB = sm;
    float* BsB = sm + 2 * ABUF;

    const int z = blockIdx.z;
    const float* B    = (z == 0) ? B0 : (z == 1) ? B1 : B2;
    const float* bias = (z == 0) ? bias0 : (z == 1) ? bias1 : bias2;
    float* C          = (z == 0) ? C0 : (z == 1) ? C1 : C2;

    const int tid  = threadIdx.x;
    const int bm   = blockIdx.y * 128;
    const int bn   = blockIdx.x * 128;
    const int lane = tid & 31;
    const int warp = tid >> 5;
    const int g    = lane >> 2;
    const int t    = lane & 3;
    const int m0   = (warp & 1) * 64;
    const int n0   = (warp >> 1) * 32;

    float acc[4][4][4];
    #pragma unroll
    for (int i = 0; i < 4; i++)
        #pragma unroll
        for (int j = 0; j < 4; j++)
            #pragma unroll
            for (int e = 0; e < 4; e++) acc[i][j][e] = 0.f;

    const int ar = tid >> 1;
    const int ac = (tid & 1) * 16;
    const int br = tid >> 3;
    const int bc = (tid & 7) * 16;

    // precomputed padded B column index for fragment reads (per nf)
    int cnp[4];
    #pragma unroll
    for (int nf = 0; nf < 4; nf++) {
        const int cb = n0 + nf * 8;
        cnp[nf] = cb + ((cb >> 5) << 2) + g;
    }

    const int NC = K / BK;
    float4 pa[4], pb[4];

    ldg_half(A, B, K, N, bm, bn, 0, 0,  ar, ac, br, bc, pa, pb);
    sts_half(AsB, BsB, 0,  ar, ac, br, bc, pa, pb);
    ldg_half(A, B, K, N, bm, bn, 0, 32, ar, ac, br, bc, pa, pb);
    sts_half(AsB, BsB, 32, ar, ac, br, bc, pa, pb);
    __syncthreads();

    for (int c = 0; c < NC; c++) {
        const int buf = c & 1;
        const int nb  = buf ^ 1;
        const uint32_t* Au = (const uint32_t*)(AsB + buf * ABUF);
        const uint32_t* Bu = (const uint32_t*)(BsB + buf * BBUF);
        float* Ad = AsB + nb * ABUF;
        float* Bd = BsB + nb * BBUF;
        const bool more = (c + 1 < NC);

        if (more) ldg_half(A, B, K, N, bm, bn, (c + 1) * BK, 0, ar, ac, br, bc, pa, pb);

        #pragma unroll
        for (int ks = 0; ks < 4; ks++) {
            const int kk = ks * 8;
            uint32_t af[4][4];
            #pragma unroll
            for (int mf = 0; mf < 4; mf++) {
                const int r = m0 + mf * 16 + g;
                af[mf][0] = Au[r * ASTRIDE + kk + t];
                af[mf][1] = Au[(r + 8) * ASTRIDE + kk + t];
                af[mf][2] = Au[r * ASTRIDE + kk + t + 4];
                af[mf][3] = Au[(r + 8) * ASTRIDE + kk + t + 4];
            }
            #pragma unroll
            for (int nf = 0; nf < 4; nf++) {
                uint32_t b0 = Bu[(kk + t) * BSTRIDE + cnp[nf]];
                uint32_t b1 = Bu[(kk + t + 4) * BSTRIDE + cnp[nf]];
                #pragma unroll
                for (int mf = 0; mf < 4; mf++)
                    mma_tf32(acc[mf][nf], af[mf][0], af[mf][1], af[mf][2], af[mf][3], b0, b1);
            }
        }

        if (more) {
            sts_half(Ad, Bd, 0, ar, ac, br, bc, pa, pb);
            ldg_half(A, B, K, N, bm, bn, (c + 1) * BK, 32, ar, ac, br, bc, pa, pb);
        }

        #pragma unroll
        for (int ks = 4; ks < 8; ks++) {
            const int kk = ks * 8;
            uint32_t af[4][4];
            #pragma unroll
            for (int mf = 0; mf < 4; mf++) {
                const int r = m0 + mf * 16 + g;
                af[mf][0] = Au[r * ASTRIDE + kk + t];
                af[mf][1] = Au[(r + 8) * ASTRIDE + kk + t];
                af[mf][2] = Au[r * ASTRIDE + kk + t + 4];
                af[mf][3] = Au[(r + 8) * ASTRIDE + kk + t + 4];
            }
            #pragma unroll
            for (int nf = 0; nf < 4; nf++) {
                uint32_t b0 = Bu[(kk + t) * BSTRIDE + cnp[nf]];
                uint32_t b1 = Bu[(kk + t + 4) * BSTRIDE + cnp[nf]];
                #pragma unroll
                for (int mf = 0; mf < 4; mf++)
                    mma_tf32(acc[mf][nf], af[mf][0], af[mf][1], af[mf][2], af[mf][3], b0, b1);
            }
        }

        if (more) {
            sts_half(Ad, Bd, 32, ar, ac, br, bc, pa, pb);
            __syncthreads();
        }
    }

    #pragma unroll
    for (int mf = 0; mf < 4; mf++) {
        const int r0 = bm + m0 + mf * 16 + g;
        #pragma unroll
        for (int nf = 0; nf < 4; nf++) {
            const int col = bn + n0 + nf * 8 + 2 * t;
            const float b0 = bias[col], b1 = bias[col + 1];
            float2 o0, o1;
            o0.x = acc[mf][nf][0] + b0; o0.y = acc[mf][nf][1] + b1;
            o1.x = acc[mf][nf][2] + b0; o1.y = acc[mf][nf][3] + b1;
            if (do_relu) {
                o0.x = fmaxf(o0.x, 0.f); o0.y = fmaxf(o0.y, 0.f);
                o1.x = fmaxf(o1.x, 0.f); o1.y = fmaxf(o1.y, 0.f);
            }
            *(float2*)(C + (size_t)r0 * N + col)       = o0;
            *(float2*)(C + (size_t)(r0 + 8) * N + col) = o1;
        }
    }
}

// ---------------- FAVOR feature map (fused q/k via blockIdx.y) ----------------
__global__ __launch_bounds__(256) void favor_kernel(
    const float* __restrict__ X0, const float* __restrict__ X1,
    const float* __restrict__ omega,
    float* __restrict__ P0, float* __restrict__ P1)
{
    __shared__ float om[DH * 32];
    __shared__ float xsb[8][DH];

    const float* X = blockIdx.y ? X1 : X0;
    float* Phi     = blockIdx.y ? P1 : P0;

    const int tid = threadIdx.x;
    for (int i = tid; i < DH * 32; i += 256) om[i] = omega[i];

    const int w    = tid >> 5;
    const int lane = tid & 31;
    const int gw   = blockIdx.x * 8 + w;
    const int token = gw >> 4;
    const int head  = gw & 15;

    const float scale = 0.35355339059327373f;   // 64^-0.25
    const size_t base = (size_t)token * D_MODEL + head * DH;

    float x0 = X[base + lane]      * scale;
    float x1 = X[base + 32 + lane] * scale;
    xsb[w][lane]      = x0;
    xsb[w][lane + 32] = x1;

    float hh = x0 * x0 + x1 * x1;
    #pragma unroll
    for (int o = 16; o; o >>= 1) hh += __shfl_xor_sync(0xffffffffu, hh, o);
    hh *= 0.5f;

    __syncthreads();

    float u = 0.f;
    #pragma unroll
    for (int d = 0; d < DH; d++)
        u = fmaf(xsb[w][d], om[d * 32 + lane], u);

    const float c = 0.125f;   // 64^-0.5
    Phi[base + lane]      = expf(u  - hh) * c;
    Phi[base + 32 + lane] = expf(-u - hh) * c;
}

// ============ chunked causal linear attention (token-parallel) ============
#define CST 68   // smem tile stride (words)

__device__ __forceinline__ void load_tile(
    float* dst, const float* __restrict__ src, size_t gbase, int tid)
{
    const int t = tid >> 2;
    const int qo = (tid & 3) * 16;
    const float* p = src + gbase + (size_t)t * D_MODEL + qo;
    float* d = dst + t * CST + qo;
    #pragma unroll
    for (int i = 0; i < 4; i++)
        *(float4*)(d + i * 4) = *(const float4*)(p + i * 4);
}

// Phase 1: S_c[m][d] = sum_t k[t][m] v[t][d] ; z_c[m] = sum_t k[t][m]
__global__ __launch_bounds__(256) void chunk_sums_kernel(
    const float* __restrict__ Kf, const float* __restrict__ V,
    float* __restrict__ gS, float* __restrict__ gZ)
{
    __shared__ float ks[64 * CST];
    __shared__ float vs[64 * CST];

    const int ch = blockIdx.x;
    const int bh = blockIdx.y;
    const int tid = threadIdx.x;
    const int b = bh >> 4, hd = bh & 15;
    const size_t gbase = (size_t)b * 1024 * D_MODEL + (size_t)(ch * CLEN) * D_MODEL + hd * DH;

    load_tile(ks, Kf, gbase, tid);
    load_tile(vs, V,  gbase, tid);
    __syncthreads();

    const int mg = (tid >> 4) * 4;
    const int dg = (tid & 15) * 4;

    float acc[4][4];
    float zz[4];
    #pragma unroll
    for (int e = 0; e < 4; e++) {
        zz[e] = 0.f;
        #pragma unroll
        for (int c = 0; c < 4; c++) acc[e][c] = 0.f;
    }

    #pragma unroll 4
    for (int t = 0; t < CLEN; t++) {
        float4 v4 = *(const float4*)(vs + t * CST + dg);
        #pragma unroll
        for (int e = 0; e < 4; e++) {
            const float kv = ks[t * CST + mg + e];
            zz[e] += kv;
            acc[e][0] = fmaf(kv, v4.x, acc[e][0]);
            acc[e][1] = fmaf(kv, v4.y, acc[e][1]);
            acc[e][2] = fmaf(kv, v4.z, acc[e][2]);
            acc[e][3] = fmaf(kv, v4.w, acc[e][3]);
        }
    }

    const size_t idx = (size_t)(bh * NCHUNK + ch);
    #pragma unroll
    for (int e = 0; e < 4; e++)
        *(float4*)(gS + idx * 4096 + (size_t)(mg + e) * 64 + dg) =
            make_float4(acc[e][0], acc[e][1], acc[e][2], acc[e][3]);
    if ((tid & 15) == 0) {
        #pragma unroll
        for (int e = 0; e < 4; e++) gZ[idx * 64 + mg + e] = zz[e];
    }
}

// Phase 2: exclusive prefix over chunks (in-place), per (b,h)
__global__ __launch_bounds__(64) void chunk_prefix_kernel(
    float* __restrict__ gS, float* __restrict__ gZ)
{
    const int bh = blockIdx.x;
    const int d  = threadIdx.x;

    float run[64];
    #pragma unroll
    for (int m = 0; m < 64; m++) run[m] = 0.f;
    float zrun = 0.f;

    for (int ch = 0; ch < NCHUNK; ch++) {
        const size_t idx = (size_t)(bh * NCHUNK + ch);
        float* Sp = gS + idx * 4096;
        float tmp[64];
        #pragma unroll
        for (int m = 0; m < 64; m++) tmp[m] = Sp[m * 64 + d];
        #pragma unroll
        for (int m = 0; m < 64; m++) { Sp[m * 64 + d] = run[m]; run[m] += tmp[m]; }
        float zt = gZ[idx * 64 + d];
        gZ[idx * 64 + d] = zrun;
        zrun += zt;
    }
}

// Phase 3: token-parallel intra-chunk attention.
__global__ __launch_bounds__(256) void chunk_attn_kernel(
    const float* __restrict__ Qf, const float* __restrict__ Kf,
    const float* __restrict__ V, const float* __restrict__ gS,
    const float* __restrict__ gZ, float* __restrict__ Out)
{
    extern __shared__ float smw[];
    float* qs = smw;                 // [i][m]
    float* kt = smw + 64 * CST;      // [m][j]
    float* vs = smw + 2 * 64 * CST;  // [j][d]
    float* Sp = smw + 3 * 64 * CST;  // [m][d]
    float* Am = smw + 4 * 64 * CST;  // [i][j]
    float* zp = smw + 5 * 64 * CST;  // [m]

    const int ch = blockIdx.x;
    const int bh = blockIdx.y;
    const int tid = threadIdx.x;
    const int b = bh >> 4, hd = bh & 15;
    const size_t gbase = (size_t)b * 1024 * D_MODEL + (size_t)(ch * CLEN) * D_MODEL + hd * DH;
    const size_t idx = (size_t)(bh * NCHUNK + ch);

    load_tile(qs, Qf, gbase, tid);
    load_tile(vs, V,  gbase, tid);
    {
        const int t = tid >> 2;
        const int qo = (tid & 3) * 16;
        const float* p = Kf + gbase + (size_t)t * D_MODEL + qo;
        #pragma unroll
        for (int i = 0; i < 16; i += 4) {
            float4 kv = *(const float4*)(p + i);
            kt[(qo + i + 0) * CST + t] = kv.x;
            kt[(qo + i + 1) * CST + t] = kv.y;
            kt[(qo + i + 2) * CST + t] = kv.z;
            kt[(qo + i + 3) * CST + t] = kv.w;
        }
    }
    {
        const int m = tid >> 2;
        const int qo = (tid & 3) * 16;
        const float* p = gS + idx * 4096 + (size_t)m * 64 + qo;
        float* dp = Sp + m * CST + qo;
        #pragma unroll
        for (int i = 0; i < 4; i++)
            *(float4*)(dp + i * 4) = *(const float4*)(p + i * 4);
    }
    if (tid < 64) zp[tid] = gZ[idx * 64 + tid];
    __syncthreads();

    const int ig = (tid >> 4) * 4;
    const int jg = (tid & 15) * 4;

    float a[4][4];
    float qz[4];
    #pragma unroll
    for (int e = 0; e < 4; e++) {
        qz[e] = 0.f;
        #pragma unroll
        for (int c = 0; c < 4; c++) a[e][c] = 0.f;
    }
    #pragma unroll 4
    for (int m = 0; m < DH; m++) {
        const float zv = zp[m];
        float4 k4 = *(const float4*)(kt + m * CST + jg);
        #pragma unroll
        for (int e = 0; e < 4; e++) {
            const float qv = qs[(ig + e) * CST + m];
            qz[e] = fmaf(qv, zv, qz[e]);
            a[e][0] = fmaf(qv, k4.x, a[e][0]);
            a[e][1] = fmaf(qv, k4.y, a[e][1]);
            a[e][2] = fmaf(qv, k4.z, a[e][2]);
            a[e][3] = fmaf(qv, k4.w, a[e][3]);
        }
    }
    float den[4];
    #pragma unroll
    for (int e = 0; e < 4; e++) {
        const int i = ig + e;
        #pragma unroll
        for (int c = 0; c < 4; c++)
            if (jg + c > i) a[e][c] = 0.f;
        float rs = a[e][0] + a[e][1] + a[e][2] + a[e][3];
        rs += __shfl_xor_sync(0xffffffffu, rs, 1);
        rs += __shfl_xor_sync(0xffffffffu, rs, 2);
        rs += __shfl_xor_sync(0xffffffffu, rs, 4);
        rs += __shfl_xor_sync(0xffffffffu, rs, 8);
        den[e] = qz[e] + rs + 1e-6f;
        *(float4*)(Am + i * CST + jg) = make_float4(a[e][0], a[e][1], a[e][2], a[e][3]);
    }
    __syncthreads();

    float acc[4][4];
    #pragma unroll
    for (int e = 0; e < 4; e++)
        #pragma unroll
        for (int c = 0; c < 4; c++) acc[e][c] = 0.f;

    #pragma unroll 4
    for (int m = 0; m < DH; m++) {
        float4 s4 = *(const float4*)(Sp + m * CST + jg);
        #pragma unroll
        for (int e = 0; e < 4; e++) {
            const float qv = qs[(ig + e) * CST + m];
            acc[e][0] = fmaf(qv, s4.x, acc[e][0]);
            acc[e][1] = fmaf(qv, s4.y, acc[e][1]);
            acc[e][2] = fmaf(qv, s4.z, acc[e][2]);
            acc[e][3] = fmaf(qv, s4.w, acc[e][3]);
        }
    }
    const int jmax = ig + 3;
    for (int j = 0; j <= jmax; j++) {
        float4 v4 = *(const float4*)(vs + j * CST + jg);
        #pragma unroll
        for (int e = 0; e < 4; e++) {
            const float av = Am[(ig + e) * CST + j];
            acc[e][0] = fmaf(av, v4.x, acc[e][0]);
            acc[e][1] = fmaf(av, v4.y, acc[e][1]);
            acc[e][2] = fmaf(av, v4.z, acc[e][2]);
            acc[e][3] = fmaf(av, v4.w, acc[e][3]);
        }
    }

    #pragma unroll
    for (int e = 0; e < 4; e++) {
        const float inv = 1.f / den[e];
        float* op = Out + gbase + (size_t)(ig + e) * D_MODEL + jg;
        *(float4*)op = make_float4(acc[e][0] * inv, acc[e][1] * inv,
                                   acc[e][2] * inv, acc[e][3] * inv);
    }
}
#define ATTN_SMEM ((5 * 64 * CST + 64) * 4)

// ---------------- LayerNorm(out = LN(a + r) * g + b) ----------------
__global__ __launch_bounds__(256) void ln_kernel(
    float* __restrict__ out, const float* __restrict__ a,
    const float* __restrict__ r, const float* __restrict__ gam,
    const float* __restrict__ bet)
{
    const int row = blockIdx.x;
    const int tid = threadIdx.x;
    const float* pa = a + (size_t)row * D_MODEL;
    const float* pr = r + (size_t)row * D_MODEL;

    float v[4];
    float s = 0.f, ss = 0.f;
    #pragma unroll
    for (int i = 0; i < 4; i++) {
        int idx = tid + i * 256;
        float t = pa[idx] + pr[idx];
        v[i] = t; s += t; ss = fmaf(t, t, ss);
    }

    __shared__ float red[18];
    #pragma unroll
    for (int o = 16; o; o >>= 1) {
        s  += __shfl_xor_sync(0xffffffffu, s,  o);
        ss += __shfl_xor_sync(0xffffffffu, ss, o);
    }
    const int w = tid >> 5, lane = tid & 31;
    __shared__ float rw[16];
    if (lane == 0) { rw[w] = s; rw[w + 8] = ss; }
    __syncthreads();
    if (tid == 0) {
        float S0 = 0.f, S1 = 0.f;
        #pragma unroll
        for (int i = 0; i < 8; i++) { S0 += rw[i]; S1 += rw[i + 8]; }
        red[16] = S0; red[17] = S1;
    }
    __syncthreads();

    const float mean = red[16] * (1.f / 1024.f);
    const float var  = red[17] * (1.f / 1024.f) - mean * mean;
    const float inv  = rsqrtf(var + 1e-5f);

    float* po = out + (size_t)row * D_MODEL;
    #pragma unroll
    for (int i = 0; i < 4; i++) {
        int idx = tid + i * 256;
        po[idx] = (v[i] - mean) * inv * gam[idx] + bet[idx];
    }
}

// ---------------- launch ----------------
extern "C" void kernel_launch(void* const* d_in, const int* in_sizes, int n_in,
                              void* d_out, int out_size)
{
    const float* x    = (const float*)d_in[0];
    const float* Wq   = (const float*)d_in[1];
    const float* bq   = (const float*)d_in[2];
    const float* Wk   = (const float*)d_in[3];
    const float* bk   = (const float*)d_in[4];
    const float* Wv   = (const float*)d_in[5];
    const float* bv   = (const float*)d_in[6];
    const float* Wo   = (const float*)d_in[7];
    const float* bo   = (const float*)d_in[8];
    const float* omg  = (const float*)d_in[9];
    const float* ln1g = (const float*)d_in[10];
    const float* ln1b = (const float*)d_in[11];
    const float* ln2g = (const float*)d_in[12];
    const float* ln2b = (const float*)d_in[13];
    const float* W1   = (const float*)d_in[14];
    const float* bf1  = (const float*)d_in[15];
    const float* W2   = (const float*)d_in[16];
    const float* bf2  = (const float*)d_in[17];
    float* out = (float*)d_out;

    float *cur, *q, *k, *v, *qf, *kf, *h, *ffn, *gS, *gZ;
    cudaGetSymbolAddress((void**)&cur, g_cur);
    cudaGetSymbolAddress((void**)&q,   g_q);
    cudaGetSymbolAddress((void**)&k,   g_k);
    cudaGetSymbolAddress((void**)&v,   g_v);
    cudaGetSymbolAddress((void**)&qf,  g_qf);
    cudaGetSymbolAddress((void**)&kf,  g_kf);
    cudaGetSymbolAddress((void**)&h,   g_h);
    cudaGetSymbolAddress((void**)&ffn, g_ffn);
    cudaGetSymbolAddress((void**)&gS,  g_S);
    cudaGetSymbolAddress((void**)&gZ,  g_Z);

    cudaFuncSetAttribute(mma_gemm, cudaFuncAttributeMaxDynamicSharedMemorySize, GEMM_SMEM);
    cudaFuncSetAttribute(chunk_attn_kernel, cudaFuncAttributeMaxDynamicSharedMemorySize, ATTN_SMEM);

    const dim3 gQKV(D_MODEL / 128, NTOK / 128, 3);
    const dim3 gD(D_MODEL / 128, NTOK / 128, 1);
    const dim3 gF(DFF_DIM / 128, NTOK / 128, 1);
    const dim3 gCh(NCHUNK, 32);
    const dim3 gFav(NTOK * NHEAD / 8, 2);

    for (int l = 0; l < NLAYER; l++) {
        const size_t wDD  = (size_t)l * D_MODEL * D_MODEL;
        const size_t wDF  = (size_t)l * D_MODEL * DFF_DIM;
        const size_t bD   = (size_t)l * D_MODEL;
        const size_t bF   = (size_t)l * DFF_DIM;
        const size_t oOff = (size_t)l * DH * 32;
        const float* inA  = (l == 0) ? x : cur;   // layer-0 reads x directly

        mma_gemm<<<gQKV, 256, GEMM_SMEM>>>(inA,
            Wq + wDD, Wk + wDD, Wv + wDD,
            bq + bD, bk + bD, bv + bD,
            q, k, v, NTOK, D_MODEL, D_MODEL, 0);

        favor_kernel<<<gFav, 256>>>(q, k, omg + oOff, qf, kf);

        chunk_sums_kernel<<<gCh, 256>>>(kf, v, gS, gZ);
        chunk_prefix_kernel<<<32, 64>>>(gS, gZ);
        chunk_attn_kernel<<<gCh, 256, ATTN_SMEM>>>(qf, kf, v, gS, gZ, q);  // attn -> q

        mma_gemm<<<gD, 256, GEMM_SMEM>>>(q,
            Wo + wDD, Wo + wDD, Wo + wDD,
            bo + bD, bo + bD, bo + bD,
            k, k, k, NTOK, D_MODEL, D_MODEL, 0);
        ln_kernel<<<NTOK, 256>>>(h, inA, k, ln1g + bD, ln1b + bD);

        mma_gemm<<<gF, 256, GEMM_SMEM>>>(h,
            W1 + wDF, W1 + wDF, W1 + wDF,
            bf1 + bF, bf1 + bF, bf1 + bF,
            ffn, ffn, ffn, NTOK, DFF_DIM, D_MODEL, 1);
        mma_gemm<<<gD, 256, GEMM_SMEM>>>(ffn,
            W2 + wDF, W2 + wDF, W2 + wDF,
            bf2 + bD, bf2 + bD, bf2 + bD,
            v, v, v, NTOK, D_MODEL, DFF_DIM, 0);

        float* dst = (l == NLAYER - 1) ? out : cur;
        ln_kernel<<<NTOK, 256>>>(dst, h, v, ln2g + bD, ln2b + bD);
    }
}

// round 9
// speedup vs baseline: 1.4322x; 1.1311x over previous
#include <cuda_runtime.h>
#include <cstdint>
#include <math.h>

// ---------------- problem constants ----------------
#define D_MODEL 1024
#define DFF_DIM 4096
#define NTOK    2048          // B*S = 2*1024
#define NHEAD   16
#define DH      64
#define NLAYER  3
#define NCHUNK  16            // chunks per sequence
#define CLEN    64            // tokens per chunk

// ---------------- scratch (no allocs allowed) ----------------
__device__ float g_cur[NTOK * D_MODEL];
__device__ float g_q  [NTOK * D_MODEL];
__device__ float g_k  [NTOK * D_MODEL];
__device__ float g_v  [NTOK * D_MODEL];
__device__ float g_qf [NTOK * D_MODEL];
__device__ float g_kf [NTOK * D_MODEL];
__device__ float g_h  [NTOK * D_MODEL];
__device__ float g_ffn[NTOK * DFF_DIM];
__device__ float g_S  [32 * NCHUNK * DH * DH];
__device__ float g_Z  [32 * NCHUNK * DH];

// ================= helpers =================
__device__ __forceinline__ uint32_t f2tf32(float f) {
    uint32_t u;
    asm("cvt.rna.tf32.f32 %0, %1;" : "=r"(u) : "f"(f));
    return u;
}
__device__ __forceinline__ void mma_tf32(float c[4], uint32_t a0, uint32_t a1,
                                         uint32_t a2, uint32_t a3,
                                         uint32_t b0, uint32_t b1) {
    asm volatile(
        "mma.sync.aligned.m16n8k8.row.col.f32.tf32.tf32.f32 "
        "{%0,%1,%2,%3}, {%4,%5,%6,%7}, {%8,%9}, {%0,%1,%2,%3};"
        : "+f"(c[0]), "+f"(c[1]), "+f"(c[2]), "+f"(c[3])
        : "r"(a0), "r"(a1), "r"(a2), "r"(a3), "r"(b0), "r"(b1));
}

// ================= TF32 tensor-core GEMM (proven, unchanged) =================
#define BK      64
#define ASTRIDE 68
#define BSTRIDE 168
#define ABUF (128 * ASTRIDE)
#define BBUF (64 * BSTRIDE)
#define GEMM_SMEM ((2 * ABUF + 2 * BBUF) * 4)

__device__ __forceinline__ void ldg_half(
    const float* __restrict__ A, const float* __restrict__ B,
    int K, int N, int bm, int bn, int k0, int koff,
    int ar, int ac, int br, int bc, float4 pa[4], float4 pb[4])
{
    const float* Ap = A + (size_t)(bm + ar) * K + k0 + koff + ac;
    #pragma unroll
    for (int i = 0; i < 4; i++) pa[i] = *(const float4*)(Ap + i * 4);
    const float* Bp = B + (size_t)(k0 + koff + br) * N + bn + bc;
    #pragma unroll
    for (int i = 0; i < 4; i++) pb[i] = *(const float4*)(Bp + i * 4);
}
__device__ __forceinline__ void sts_half(
    float* Ad, float* Bd, int koff,
    int ar, int ac, int br, int bc, const float4 pa[4], const float4 pb[4])
{
    #pragma unroll
    for (int i = 0; i < 4; i++) {
        uint4 u;
        u.x = f2tf32(pa[i].x); u.y = f2tf32(pa[i].y);
        u.z = f2tf32(pa[i].z); u.w = f2tf32(pa[i].w);
        *(uint4*)(Ad + ar * ASTRIDE + koff + ac + i * 4) = u;
    }
    const int bcp = bc + ((bc >> 5) << 2);
    #pragma unroll
    for (int i = 0; i < 4; i++) {
        uint4 u;
        u.x = f2tf32(pb[i].x); u.y = f2tf32(pb[i].y);
        u.z = f2tf32(pb[i].z); u.w = f2tf32(pb[i].w);
        *(uint4*)(Bd + (koff + br) * BSTRIDE + bcp + i * 4) = u;
    }
}

__global__ __launch_bounds__(256, 1) void mma_gemm(
    const float* __restrict__ A,
    const float* __restrict__ B0, const float* __restrict__ B1, const float* __restrict__ B2,
    const float* __restrict__ bias0, const float* __restrict__ bias1, const float* __restrict__ bias2,
    float* __restrict__ C0, float* __restrict__ C1, float* __restrict__ C2,
    int M, int N, int K, int do_relu)
{
    extern __shared__ float sm[];
    float* AsB = sm;
    float* BsB = sm + 2 * ABUF;

    const int z = blockIdx.z;
    const float* B    = (z == 0) ? B0 : (z == 1) ? B1 : B2;
    const float* bias = (z == 0) ? bias0 : (z == 1) ? bias1 : bias2;
    float* C          = (z == 0) ? C0 : (z == 1) ? C1 : C2;

    const int tid  = threadIdx.x;
    const int bm   = blockIdx.y * 128;
    const int bn   = blockIdx.x * 128;
    const int lane = tid & 31;
    const int warp = tid >> 5;
    const int g    = lane >> 2;
    const int t    = lane & 3;
    const int m0   = (warp & 1) * 64;
    const int n0   = (warp >> 1) * 32;

    float acc[4][4][4];
    #pragma unroll
    for (int i = 0; i < 4; i++)
        #pragma unroll
        for (int j = 0; j < 4; j++)
            #pragma unroll
            for (int e = 0; e < 4; e++) acc[i][j][e] = 0.f;

    const int ar = tid >> 1;
    const int ac = (tid & 1) * 16;
    const int br = tid >> 3;
    const int bc = (tid & 7) * 16;

    int cnp[4];
    #pragma unroll
    for (int nf = 0; nf < 4; nf++) {
        const int cb = n0 + nf * 8;
        cnp[nf] = cb + ((cb >> 5) << 2) + g;
    }

    const int NC = K / BK;
    float4 pa[4], pb[4];

    ldg_half(A, B, K, N, bm, bn, 0, 0,  ar, ac, br, bc, pa, pb);
    sts_half(AsB, BsB, 0,  ar, ac, br, bc, pa, pb);
    ldg_half(A, B, K, N, bm, bn, 0, 32, ar, ac, br, bc, pa, pb);
    sts_half(AsB, BsB, 32, ar, ac, br, bc, pa, pb);
    __syncthreads();

    for (int c = 0; c < NC; c++) {
        const int buf = c & 1;
        const int nb  = buf ^ 1;
        const uint32_t* Au = (const uint32_t*)(AsB + buf * ABUF);
        const uint32_t* Bu = (const uint32_t*)(BsB + buf * BBUF);
        float* Ad = AsB + nb * ABUF;
        float* Bd = BsB + nb * BBUF;
        const bool more = (c + 1 < NC);

        if (more) ldg_half(A, B, K, N, bm, bn, (c + 1) * BK, 0, ar, ac, br, bc, pa, pb);

        #pragma unroll
        for (int ks = 0; ks < 4; ks++) {
            const int kk = ks * 8;
            uint32_t af[4][4];
            #pragma unroll
            for (int mf = 0; mf < 4; mf++) {
                const int r = m0 + mf * 16 + g;
                af[mf][0] = Au[r * ASTRIDE + kk + t];
                af[mf][1] = Au[(r + 8) * ASTRIDE + kk + t];
                af[mf][2] = Au[r * ASTRIDE + kk + t + 4];
                af[mf][3] = Au[(r + 8) * ASTRIDE + kk + t + 4];
            }
            #pragma unroll
            for (int nf = 0; nf < 4; nf++) {
                uint32_t b0 = Bu[(kk + t) * BSTRIDE + cnp[nf]];
                uint32_t b1 = Bu[(kk + t + 4) * BSTRIDE + cnp[nf]];
                #pragma unroll
                for (int mf = 0; mf < 4; mf++)
                    mma_tf32(acc[mf][nf], af[mf][0], af[mf][1], af[mf][2], af[mf][3], b0, b1);
            }
        }

        if (more) {
            sts_half(Ad, Bd, 0, ar, ac, br, bc, pa, pb);
            ldg_half(A, B, K, N, bm, bn, (c + 1) * BK, 32, ar, ac, br, bc, pa, pb);
        }

        #pragma unroll
        for (int ks = 4; ks < 8; ks++) {
            const int kk = ks * 8;
            uint32_t af[4][4];
            #pragma unroll
            for (int mf = 0; mf < 4; mf++) {
                const int r = m0 + mf * 16 + g;
                af[mf][0] = Au[r * ASTRIDE + kk + t];
                af[mf][1] = Au[(r + 8) * ASTRIDE + kk + t];
                af[mf][2] = Au[r * ASTRIDE + kk + t + 4];
                af[mf][3] = Au[(r + 8) * ASTRIDE + kk + t + 4];
            }
            #pragma unroll
            for (int nf = 0; nf < 4; nf++) {
                uint32_t b0 = Bu[(kk + t) * BSTRIDE + cnp[nf]];
                uint32_t b1 = Bu[(kk + t + 4) * BSTRIDE + cnp[nf]];
                #pragma unroll
                for (int mf = 0; mf < 4; mf++)
                    mma_tf32(acc[mf][nf], af[mf][0], af[mf][1], af[mf][2], af[mf][3], b0, b1);
            }
        }

        if (more) {
            sts_half(Ad, Bd, 32, ar, ac, br, bc, pa, pb);
            __syncthreads();
        }
    }

    #pragma unroll
    for (int mf = 0; mf < 4; mf++) {
        const int r0 = bm + m0 + mf * 16 + g;
        #pragma unroll
        for (int nf = 0; nf < 4; nf++) {
            const int col = bn + n0 + nf * 8 + 2 * t;
            const float b0 = bias[col], b1 = bias[col + 1];
            float2 o0, o1;
            o0.x = acc[mf][nf][0] + b0; o0.y = acc[mf][nf][1] + b1;
            o1.x = acc[mf][nf][2] + b0; o1.y = acc[mf][nf][3] + b1;
            if (do_relu) {
                o0.x = fmaxf(o0.x, 0.f); o0.y = fmaxf(o0.y, 0.f);
                o1.x = fmaxf(o1.x, 0.f); o1.y = fmaxf(o1.y, 0.f);
            }
            *(float2*)(C + (size_t)r0 * N + col)       = o0;
            *(float2*)(C + (size_t)(r0 + 8) * N + col) = o1;
        }
    }
}

// ---------------- FAVOR feature map (fused q/k via blockIdx.y) ----------------
__global__ __launch_bounds__(256) void favor_kernel(
    const float* __restrict__ X0, const float* __restrict__ X1,
    const float* __restrict__ omega,
    float* __restrict__ P0, float* __restrict__ P1)
{
    __shared__ float om[DH * 32];
    __shared__ float xsb[8][DH];

    const float* X = blockIdx.y ? X1 : X0;
    float* Phi     = blockIdx.y ? P1 : P0;

    const int tid = threadIdx.x;
    for (int i = tid; i < DH * 32; i += 256) om[i] = omega[i];

    const int w    = tid >> 5;
    const int lane = tid & 31;
    const int gw   = blockIdx.x * 8 + w;
    const int token = gw >> 4;
    const int head  = gw & 15;

    const float scale = 0.35355339059327373f;   // 64^-0.25
    const size_t base = (size_t)token * D_MODEL + head * DH;

    float x0 = X[base + lane]      * scale;
    float x1 = X[base + 32 + lane] * scale;
    xsb[w][lane]      = x0;
    xsb[w][lane + 32] = x1;

    float hh = x0 * x0 + x1 * x1;
    #pragma unroll
    for (int o = 16; o; o >>= 1) hh += __shfl_xor_sync(0xffffffffu, hh, o);
    hh *= 0.5f;

    __syncthreads();

    float u = 0.f;
    #pragma unroll
    for (int d = 0; d < DH; d++)
        u = fmaf(xsb[w][d], om[d * 32 + lane], u);

    const float c = 0.125f;   // 64^-0.5
    Phi[base + lane]      = expf(u  - hh) * c;
    Phi[base + 32 + lane] = expf(-u - hh) * c;
}

// ============ chunked causal linear attention (token-parallel) ============
#define CST 68   // smem tile stride (words)

__device__ __forceinline__ void load_tile(
    float* dst, const float* __restrict__ src, size_t gbase, int tid)
{
    const int t = tid >> 2;
    const int qo = (tid & 3) * 16;
    const float* p = src + gbase + (size_t)t * D_MODEL + qo;
    float* d = dst + t * CST + qo;
    #pragma unroll
    for (int i = 0; i < 4; i++)
        *(float4*)(d + i * 4) = *(const float4*)(p + i * 4);
}

// Phase 1: S_c[m][d] = sum_t k[t][m] v[t][d] ; z_c[m] = sum_t k[t][m]
__global__ __launch_bounds__(256) void chunk_sums_kernel(
    const float* __restrict__ Kf, const float* __restrict__ V,
    float* __restrict__ gS, float* __restrict__ gZ)
{
    __shared__ float ks[64 * CST];
    __shared__ float vs[64 * CST];

    const int ch = blockIdx.x;
    const int bh = blockIdx.y;
    const int tid = threadIdx.x;
    const int b = bh >> 4, hd = bh & 15;
    const size_t gbase = (size_t)b * 1024 * D_MODEL + (size_t)(ch * CLEN) * D_MODEL + hd * DH;

    load_tile(ks, Kf, gbase, tid);
    load_tile(vs, V,  gbase, tid);
    __syncthreads();

    const int mg = (tid >> 4) * 4;
    const int dg = (tid & 15) * 4;

    float acc[4][4];
    float zz[4];
    #pragma unroll
    for (int e = 0; e < 4; e++) {
        zz[e] = 0.f;
        #pragma unroll
        for (int c = 0; c < 4; c++) acc[e][c] = 0.f;
    }

    #pragma unroll 4
    for (int t = 0; t < CLEN; t++) {
        float4 v4 = *(const float4*)(vs + t * CST + dg);
        #pragma unroll
        for (int e = 0; e < 4; e++) {
            const float kv = ks[t * CST + mg + e];
            zz[e] += kv;
            acc[e][0] = fmaf(kv, v4.x, acc[e][0]);
            acc[e][1] = fmaf(kv, v4.y, acc[e][1]);
            acc[e][2] = fmaf(kv, v4.z, acc[e][2]);
            acc[e][3] = fmaf(kv, v4.w, acc[e][3]);
        }
    }

    const size_t idx = (size_t)(bh * NCHUNK + ch);
    #pragma unroll
    for (int e = 0; e < 4; e++)
        *(float4*)(gS + idx * 4096 + (size_t)(mg + e) * 64 + dg) =
            make_float4(acc[e][0], acc[e][1], acc[e][2], acc[e][3]);
    if ((tid & 15) == 0) {
        #pragma unroll
        for (int e = 0; e < 4; e++) gZ[idx * 64 + mg + e] = zz[e];
    }
}

// Phase 2: exclusive prefix over 16 chunks — one thread per (bh, element).
// 32*4096 threads for S; first 64 e's of each bh also handle the z chain.
__global__ __launch_bounds__(256) void chunk_prefix_kernel(
    float* __restrict__ gS, float* __restrict__ gZ)
{
    const int gid = blockIdx.x * 256 + threadIdx.x;   // 0 .. 131071
    const int bh = gid >> 12;
    const int e  = gid & 4095;

    const size_t base = (size_t)bh * (NCHUNK * 4096) + e;
    float vals[NCHUNK];
    #pragma unroll
    for (int ch = 0; ch < NCHUNK; ch++)
        vals[ch] = gS[base + (size_t)ch * 4096];

    float run = 0.f;
    #pragma unroll
    for (int ch = 0; ch < NCHUNK; ch++) {
        const float t = vals[ch];
        gS[base + (size_t)ch * 4096] = run;
        run += t;
    }

    if (e < 64) {
        const size_t zbase = (size_t)bh * (NCHUNK * 64) + e;
        float zv[NCHUNK];
        #pragma unroll
        for (int ch = 0; ch < NCHUNK; ch++)
            zv[ch] = gZ[zbase + ch * 64];
        float zr = 0.f;
        #pragma unroll
        for (int ch = 0; ch < NCHUNK; ch++) {
            const float t = zv[ch];
            gZ[zbase + ch * 64] = zr;
            zr += t;
        }
    }
}

// Phase 3: token-parallel intra-chunk attention.
__global__ __launch_bounds__(256) void chunk_attn_kernel(
    const float* __restrict__ Qf, const float* __restrict__ Kf,
    const float* __restrict__ V, const float* __restrict__ gS,
    const float* __restrict__ gZ, float* __restrict__ Out)
{
    extern __shared__ float smw[];
    float* qs = smw;                 // [i][m]
    float* kt = smw + 64 * CST;      // [m][j]
    float* vs = smw + 2 * 64 * CST;  // [j][d]
    float* Sp = smw + 3 * 64 * CST;  // [m][d]
    float* Am = smw + 4 * 64 * CST;  // [i][j]
    float* zp = smw + 5 * 64 * CST;  // [m]

    const int ch = blockIdx.x;
    const int bh = blockIdx.y;
    const int tid = threadIdx.x;
    const int b = bh >> 4, hd = bh & 15;
    const size_t gbase = (size_t)b * 1024 * D_MODEL + (size_t)(ch * CLEN) * D_MODEL + hd * DH;
    const size_t idx = (size_t)(bh * NCHUNK + ch);

    load_tile(qs, Qf, gbase, tid);
    load_tile(vs, V,  gbase, tid);
    {
        const int t = tid >> 2;
        const int qo = (tid & 3) * 16;
        const float* p = Kf + gbase + (size_t)t * D_MODEL + qo;
        #pragma unroll
        for (int i = 0; i < 16; i += 4) {
            float4 kv = *(const float4*)(p + i);
            kt[(qo + i + 0) * CST + t] = kv.x;
            kt[(qo + i + 1) * CST + t] = kv.y;
            kt[(qo + i + 2) * CST + t] = kv.z;
            kt[(qo + i + 3) * CST + t] = kv.w;
        }
    }
    {
        const int m = tid >> 2;
        const int qo = (tid & 3) * 16;
        const float* p = gS + idx * 4096 + (size_t)m * 64 + qo;
        float* dp = Sp + m * CST + qo;
        #pragma unroll
        for (int i = 0; i < 4; i++)
            *(float4*)(dp + i * 4) = *(const float4*)(p + i * 4);
    }
    if (tid < 64) zp[tid] = gZ[idx * 64 + tid];
    __syncthreads();

    const int ig = (tid >> 4) * 4;
    const int jg = (tid & 15) * 4;

    float a[4][4];
    float qz[4];
    #pragma unroll
    for (int e = 0; e < 4; e++) {
        qz[e] = 0.f;
        #pragma unroll
        for (int c = 0; c < 4; c++) a[e][c] = 0.f;
    }
    #pragma unroll 4
    for (int m = 0; m < DH; m++) {
        const float zv = zp[m];
        float4 k4 = *(const float4*)(kt + m * CST + jg);
        #pragma unroll
        for (int e = 0; e < 4; e++) {
            const float qv = qs[(ig + e) * CST + m];
            qz[e] = fmaf(qv, zv, qz[e]);
            a[e][0] = fmaf(qv, k4.x, a[e][0]);
            a[e][1] = fmaf(qv, k4.y, a[e][1]);
            a[e][2] = fmaf(qv, k4.z, a[e][2]);
            a[e][3] = fmaf(qv, k4.w, a[e][3]);
        }
    }
    float den[4];
    #pragma unroll
    for (int e = 0; e < 4; e++) {
        const int i = ig + e;
        #pragma unroll
        for (int c = 0; c < 4; c++)
            if (jg + c > i) a[e][c] = 0.f;
        float rs = a[e][0] + a[e][1] + a[e][2] + a[e][3];
        rs += __shfl_xor_sync(0xffffffffu, rs, 1);
        rs += __shfl_xor_sync(0xffffffffu, rs, 2);
        rs += __shfl_xor_sync(0xffffffffu, rs, 4);
        rs += __shfl_xor_sync(0xffffffffu, rs, 8);
        den[e] = qz[e] + rs + 1e-6f;
        *(float4*)(Am + i * CST + jg) = make_float4(a[e][0], a[e][1], a[e][2], a[e][3]);
    }
    __syncthreads();

    float acc[4][4];
    #pragma unroll
    for (int e = 0; e < 4; e++)
        #pragma unroll
        for (int c = 0; c < 4; c++) acc[e][c] = 0.f;

    #pragma unroll 4
    for (int m = 0; m < DH; m++) {
        float4 s4 = *(const float4*)(Sp + m * CST + jg);
        #pragma unroll
        for (int e = 0; e < 4; e++) {
            const float qv = qs[(ig + e) * CST + m];
            acc[e][0] = fmaf(qv, s4.x, acc[e][0]);
            acc[e][1] = fmaf(qv, s4.y, acc[e][1]);
            acc[e][2] = fmaf(qv, s4.z, acc[e][2]);
            acc[e][3] = fmaf(qv, s4.w, acc[e][3]);
        }
    }
    const int jmax = ig + 3;
    for (int j = 0; j <= jmax; j++) {
        float4 v4 = *(const float4*)(vs + j * CST + jg);
        #pragma unroll
        for (int e = 0; e < 4; e++) {
            const float av = Am[(ig + e) * CST + j];
            acc[e][0] = fmaf(av, v4.x, acc[e][0]);
            acc[e][1] = fmaf(av, v4.y, acc[e][1]);
            acc[e][2] = fmaf(av, v4.z, acc[e][2]);
            acc[e][3] = fmaf(av, v4.w, acc[e][3]);
        }
    }

    #pragma unroll
    for (int e = 0; e < 4; e++) {
        const float inv = 1.f / den[e];
        float* op = Out + gbase + (size_t)(ig + e) * D_MODEL + jg;
        *(float4*)op = make_float4(acc[e][0] * inv, acc[e][1] * inv,
                                   acc[e][2] * inv, acc[e][3] * inv);
    }
}
#define ATTN_SMEM ((5 * 64 * CST + 64) * 4)

// ---------------- LayerNorm(out = LN(a + r) * g + b) ----------------
__global__ __launch_bounds__(256) void ln_kernel(
    float* __restrict__ out, const float* __restrict__ a,
    const float* __restrict__ r, const float* __restrict__ gam,
    const float* __restrict__ bet)
{
    const int row = blockIdx.x;
    const int tid = threadIdx.x;
    const float* pa = a + (size_t)row * D_MODEL;
    const float* pr = r + (size_t)row * D_MODEL;

    float v[4];
    float s = 0.f, ss = 0.f;
    #pragma unroll
    for (int i = 0; i < 4; i++) {
        int idx = tid + i * 256;
        float t = pa[idx] + pr[idx];
        v[i] = t; s += t; ss = fmaf(t, t, ss);
    }

    __shared__ float red[18];
    #pragma unroll
    for (int o = 16; o; o >>= 1) {
        s  += __shfl_xor_sync(0xffffffffu, s,  o);
        ss += __shfl_xor_sync(0xffffffffu, ss, o);
    }
    const int w = tid >> 5, lane = tid & 31;
    __shared__ float rw[16];
    if (lane == 0) { rw[w] = s; rw[w + 8] = ss; }
    __syncthreads();
    if (tid == 0) {
        float S0 = 0.f, S1 = 0.f;
        #pragma unroll
        for (int i = 0; i < 8; i++) { S0 += rw[i]; S1 += rw[i + 8]; }
        red[16] = S0; red[17] = S1;
    }
    __syncthreads();

    const float mean = red[16] * (1.f / 1024.f);
    const float var  = red[17] * (1.f / 1024.f) - mean * mean;
    const float inv  = rsqrtf(var + 1e-5f);

    float* po = out + (size_t)row * D_MODEL;
    #pragma unroll
    for (int i = 0; i < 4; i++) {
        int idx = tid + i * 256;
        po[idx] = (v[i] - mean) * inv * gam[idx] + bet[idx];
    }
}

// ---------------- launch ----------------
extern "C" void kernel_launch(void* const* d_in, const int* in_sizes, int n_in,
                              void* d_out, int out_size)
{
    const float* x    = (const float*)d_in[0];
    const float* Wq   = (const float*)d_in[1];
    const float* bq   = (const float*)d_in[2];
    const float* Wk   = (const float*)d_in[3];
    const float* bk   = (const float*)d_in[4];
    const float* Wv   = (const float*)d_in[5];
    const float* bv   = (const float*)d_in[6];
    const float* Wo   = (const float*)d_in[7];
    const float* bo   = (const float*)d_in[8];
    const float* omg  = (const float*)d_in[9];
    const float* ln1g = (const float*)d_in[10];
    const float* ln1b = (const float*)d_in[11];
    const float* ln2g = (const float*)d_in[12];
    const float* ln2b = (const float*)d_in[13];
    const float* W1   = (const float*)d_in[14];
    const float* bf1  = (const float*)d_in[15];
    const float* W2   = (const float*)d_in[16];
    const float* bf2  = (const float*)d_in[17];
    float* out = (float*)d_out;

    float *cur, *q, *k, *v, *qf, *kf, *h, *ffn, *gS, *gZ;
    cudaGetSymbolAddress((void**)&cur, g_cur);
    cudaGetSymbolAddress((void**)&q,   g_q);
    cudaGetSymbolAddress((void**)&k,   g_k);
    cudaGetSymbolAddress((void**)&v,   g_v);
    cudaGetSymbolAddress((void**)&qf,  g_qf);
    cudaGetSymbolAddress((void**)&kf,  g_kf);
    cudaGetSymbolAddress((void**)&h,   g_h);
    cudaGetSymbolAddress((void**)&ffn, g_ffn);
    cudaGetSymbolAddress((void**)&gS,  g_S);
    cudaGetSymbolAddress((void**)&gZ,  g_Z);

    cudaFuncSetAttribute(mma_gemm, cudaFuncAttributeMaxDynamicSharedMemorySize, GEMM_SMEM);
    cudaFuncSetAttribute(chunk_attn_kernel, cudaFuncAttributeMaxDynamicSharedMemorySize, ATTN_SMEM);

    const dim3 gQKV(D_MODEL / 128, NTOK / 128, 3);
    const dim3 gD(D_MODEL / 128, NTOK / 128, 1);
    const dim3 gF(DFF_DIM / 128, NTOK / 128, 1);
    const dim3 gCh(NCHUNK, 32);
    const dim3 gFav(NTOK * NHEAD / 8, 2);
    const int  gPref = (32 * 4096) / 256;    // 512 blocks

    for (int l = 0; l < NLAYER; l++) {
        const size_t wDD  = (size_t)l * D_MODEL * D_MODEL;
        const size_t wDF  = (size_t)l * D_MODEL * DFF_DIM;
        const size_t bD   = (size_t)l * D_MODEL;
        const size_t bF   = (size_t)l * DFF_DIM;
        const size_t oOff = (size_t)l * DH * 32;
        const float* inA  = (l == 0) ? x : cur;

        mma_gemm<<<gQKV, 256, GEMM_SMEM>>>(inA,
            Wq + wDD, Wk + wDD, Wv + wDD,
            bq + bD, bk + bD, bv + bD,
            q, k, v, NTOK, D_MODEL, D_MODEL, 0);

        favor_kernel<<<gFav, 256>>>(q, k, omg + oOff, qf, kf);

        chunk_sums_kernel<<<gCh, 256>>>(kf, v, gS, gZ);
        chunk_prefix_kernel<<<gPref, 256>>>(gS, gZ);
        chunk_attn_kernel<<<gCh, 256, ATTN_SMEM>>>(qf, kf, v, gS, gZ, q);  // attn -> q

        mma_gemm<<<gD, 256, GEMM_SMEM>>>(q,
            Wo + wDD, Wo + wDD, Wo + wDD,
            bo + bD, bo + bD, bo + bD,
            k, k, k, NTOK, D_MODEL, D_MODEL, 0);
        ln_kernel<<<NTOK, 256>>>(h, inA, k, ln1g + bD, ln1b + bD);

        mma_gemm<<<gF, 256, GEMM_SMEM>>>(h,
            W1 + wDF, W1 + wDF, W1 + wDF,
            bf1 + bF, bf1 + bF, bf1 + bF,
            ffn, ffn, ffn, NTOK, DFF_DIM, D_MODEL, 1);
        mma_gemm<<<gD, 256, GEMM_SMEM>>>(ffn,
            W2 + wDF, W2 + wDF, W2 + wDF,
            bf2 + bD, bf2 + bD, bf2 + bD,
            v, v, v, NTOK, D_MODEL, DFF_DIM, 0);

        float* dst = (l == NLAYER - 1) ? out : cur;
        ln_kernel<<<NTOK, 256>>>(dst, h, v, ln2g + bD, ln2b + bD);
    }
}

// round 10
// speedup vs baseline: 1.5689x; 1.0954x over previous
#include <cuda_runtime.h>
#include <cstdint>
#include <math.h>

// ---------------- problem constants ----------------
#define D_MODEL 1024
#define DFF_DIM 4096
#define NTOK    2048          // B*S = 2*1024
#define NHEAD   16
#define DH      64
#define NLAYER  3
#define NCHUNK  16            // chunks per sequence
#define CLEN    64            // tokens per chunk

// ---------------- scratch (no allocs allowed) ----------------
__device__ float g_cur[NTOK * D_MODEL];
__device__ float g_q  [NTOK * D_MODEL];
__device__ float g_k  [NTOK * D_MODEL];
__device__ float g_v  [NTOK * D_MODEL];
__device__ float g_qf [NTOK * D_MODEL];
__device__ float g_kf [NTOK * D_MODEL];
__device__ float g_h  [NTOK * D_MODEL];
__device__ float g_ffn[NTOK * DFF_DIM];
__device__ float g_S  [32 * NCHUNK * DH * DH];
__device__ float g_Z  [32 * NCHUNK * DH];

// ================= helpers =================
__device__ __forceinline__ uint32_t f2tf32(float f) {
    uint32_t u;
    asm("cvt.rna.tf32.f32 %0, %1;" : "=r"(u) : "f"(f));
    return u;
}
__device__ __forceinline__ void mma_tf32(float c[4], uint32_t a0, uint32_t a1,
                                         uint32_t a2, uint32_t a3,
                                         uint32_t b0, uint32_t b1) {
    asm volatile(
        "mma.sync.aligned.m16n8k8.row.col.f32.tf32.tf32.f32 "
        "{%0,%1,%2,%3}, {%4,%5,%6,%7}, {%8,%9}, {%0,%1,%2,%3};"
        : "+f"(c[0]), "+f"(c[1]), "+f"(c[2]), "+f"(c[3])
        : "r"(a0), "r"(a1), "r"(a2), "r"(a3), "r"(b0), "r"(b1));
}

// ================= TF32 tensor-core GEMM — 512 threads, 16 warps =================
// 128x128 CTA tile, BK=64, warp grid 4m x 4n (warp tile 32x32).
// Smem layouts identical to the proven round-8/9 kernel.
#define BK      64
#define ASTRIDE 68
#define BSTRIDE 168
#define ABUF (128 * ASTRIDE)
#define BBUF (64 * BSTRIDE)
#define GEMM_SMEM ((2 * ABUF + 2 * BBUF) * 4)

// 512-thread staging of one 32-wide K half (8 floats per thread each for A and B)
__device__ __forceinline__ void ldg_half(
    const float* __restrict__ A, const float* __restrict__ B,
    int K, int N, int bm, int bn, int k0, int koff,
    int ar, int ac, int br, int bc, float4 pa[2], float4 pb[2])
{
    const float* Ap = A + (size_t)(bm + ar) * K + k0 + koff + ac;
    pa[0] = *(const float4*)(Ap);
    pa[1] = *(const float4*)(Ap + 4);
    const float* Bp = B + (size_t)(k0 + koff + br) * N + bn + bc;
    pb[0] = *(const float4*)(Bp);
    pb[1] = *(const float4*)(Bp + 4);
}
__device__ __forceinline__ void sts_half(
    float* Ad, float* Bd, int koff,
    int ar, int ac, int br, int bcp, const float4 pa[2], const float4 pb[2])
{
    #pragma unroll
    for (int i = 0; i < 2; i++) {
        uint4 u;
        u.x = f2tf32(pa[i].x); u.y = f2tf32(pa[i].y);
        u.z = f2tf32(pa[i].z); u.w = f2tf32(pa[i].w);
        *(uint4*)(Ad + ar * ASTRIDE + koff + ac + i * 4) = u;
    }
    #pragma unroll
    for (int i = 0; i < 2; i++) {
        uint4 u;
        u.x = f2tf32(pb[i].x); u.y = f2tf32(pb[i].y);
        u.z = f2tf32(pb[i].z); u.w = f2tf32(pb[i].w);
        *(uint4*)(Bd + (koff + br) * BSTRIDE + bcp + i * 4) = u;
    }
}

__global__ __launch_bounds__(512, 1) void mma_gemm(
    const float* __restrict__ A,
    const float* __restrict__ B0, const float* __restrict__ B1, const float* __restrict__ B2,
    const float* __restrict__ bias0, const float* __restrict__ bias1, const float* __restrict__ bias2,
    float* __restrict__ C0, float* __restrict__ C1, float* __restrict__ C2,
    int M, int N, int K, int do_relu)
{
    extern __shared__ float sm[];
    float* AsB = sm;
    float* BsB = sm + 2 * ABUF;

    const int z = blockIdx.z;
    const float* B    = (z == 0) ? B0 : (z == 1) ? B1 : B2;
    const float* bias = (z == 0) ? bias0 : (z == 1) ? bias1 : bias2;
    float* C          = (z == 0) ? C0 : (z == 1) ? C1 : C2;

    const int tid  = threadIdx.x;
    const int bm   = blockIdx.y * 128;
    const int bn   = blockIdx.x * 128;
    const int lane = tid & 31;
    const int warp = tid >> 5;          // 0..15
    const int g    = lane >> 2;
    const int t    = lane & 3;
    const int m0   = (warp & 3) * 32;   // 4 m-warps
    const int n0   = (warp >> 2) * 32;  // 4 n-warps

    float acc[2][4][4];
    #pragma unroll
    for (int i = 0; i < 2; i++)
        #pragma unroll
        for (int j = 0; j < 4; j++)
            #pragma unroll
            for (int e = 0; e < 4; e++) acc[i][j][e] = 0.f;

    // staging indices (512 threads, one 32-wide half)
    const int ar = tid >> 2;              // 0..127
    const int ac = (tid & 3) * 8;         // 0,8,16,24
    const int br = tid >> 4;              // 0..31
    const int bc = (tid & 15) * 8;        // 0..120
    const int bcp = bc + ((bc >> 5) << 2);

    int cnp[4];
    #pragma unroll
    for (int nf = 0; nf < 4; nf++) {
        const int cb = n0 + nf * 8;
        cnp[nf] = cb + ((cb >> 5) << 2) + g;
    }

    const int NC = K / BK;
    float4 pa[2], pb[2];

    ldg_half(A, B, K, N, bm, bn, 0, 0,  ar, ac, br, bc, pa, pb);
    sts_half(AsB, BsB, 0,  ar, ac, br, bcp, pa, pb);
    ldg_half(A, B, K, N, bm, bn, 0, 32, ar, ac, br, bc, pa, pb);
    sts_half(AsB, BsB, 32, ar, ac, br, bcp, pa, pb);
    __syncthreads();

    for (int c = 0; c < NC; c++) {
        const int buf = c & 1;
        const int nb  = buf ^ 1;
        const uint32_t* Au = (const uint32_t*)(AsB + buf * ABUF);
        const uint32_t* Bu = (const uint32_t*)(BsB + buf * BBUF);
        float* Ad = AsB + nb * ABUF;
        float* Bd = BsB + nb * BBUF;
        const bool more = (c + 1 < NC);

        if (more) ldg_half(A, B, K, N, bm, bn, (c + 1) * BK, 0, ar, ac, br, bc, pa, pb);

        #pragma unroll
        for (int ks = 0; ks < 4; ks++) {
            const int kk = ks * 8;
            uint32_t af[2][4];
            #pragma unroll
            for (int mf = 0; mf < 2; mf++) {
                const int r = m0 + mf * 16 + g;
                af[mf][0] = Au[r * ASTRIDE + kk + t];
                af[mf][1] = Au[(r + 8) * ASTRIDE + kk + t];
                af[mf][2] = Au[r * ASTRIDE + kk + t + 4];
                af[mf][3] = Au[(r + 8) * ASTRIDE + kk + t + 4];
            }
            #pragma unroll
            for (int nf = 0; nf < 4; nf++) {
                uint32_t b0 = Bu[(kk + t) * BSTRIDE + cnp[nf]];
                uint32_t b1 = Bu[(kk + t + 4) * BSTRIDE + cnp[nf]];
                #pragma unroll
                for (int mf = 0; mf < 2; mf++)
                    mma_tf32(acc[mf][nf], af[mf][0], af[mf][1], af[mf][2], af[mf][3], b0, b1);
            }
        }

        if (more) {
            sts_half(Ad, Bd, 0, ar, ac, br, bcp, pa, pb);
            ldg_half(A, B, K, N, bm, bn, (c + 1) * BK, 32, ar, ac, br, bc, pa, pb);
        }

        #pragma unroll
        for (int ks = 4; ks < 8; ks++) {
            const int kk = ks * 8;
            uint32_t af[2][4];
            #pragma unroll
            for (int mf = 0; mf < 2; mf++) {
                const int r = m0 + mf * 16 + g;
                af[mf][0] = Au[r * ASTRIDE + kk + t];
                af[mf][1] = Au[(r + 8) * ASTRIDE + kk + t];
                af[mf][2] = Au[r * ASTRIDE + kk + t + 4];
                af[mf][3] = Au[(r + 8) * ASTRIDE + kk + t + 4];
            }
            #pragma unroll
            for (int nf = 0; nf < 4; nf++) {
                uint32_t b0 = Bu[(kk + t) * BSTRIDE + cnp[nf]];
                uint32_t b1 = Bu[(kk + t + 4) * BSTRIDE + cnp[nf]];
                #pragma unroll
                for (int mf = 0; mf < 2; mf++)
                    mma_tf32(acc[mf][nf], af[mf][0], af[mf][1], af[mf][2], af[mf][3], b0, b1);
            }
        }

        if (more) {
            sts_half(Ad, Bd, 32, ar, ac, br, bcp, pa, pb);
            __syncthreads();
        }
    }

    #pragma unroll
    for (int mf = 0; mf < 2; mf++) {
        const int r0 = bm + m0 + mf * 16 + g;
        #pragma unroll
        for (int nf = 0; nf < 4; nf++) {
            const int col = bn + n0 + nf * 8 + 2 * t;
            const float b0 = bias[col], b1 = bias[col + 1];
            float2 o0, o1;
            o0.x = acc[mf][nf][0] + b0; o0.y = acc[mf][nf][1] + b1;
            o1.x = acc[mf][nf][2] + b0; o1.y = acc[mf][nf][3] + b1;
            if (do_relu) {
                o0.x = fmaxf(o0.x, 0.f); o0.y = fmaxf(o0.y, 0.f);
                o1.x = fmaxf(o1.x, 0.f); o1.y = fmaxf(o1.y, 0.f);
            }
            *(float2*)(C + (size_t)r0 * N + col)       = o0;
            *(float2*)(C + (size_t)(r0 + 8) * N + col) = o1;
        }
    }
}

// ---------------- FAVOR feature map (fused q/k via blockIdx.y) ----------------
__global__ __launch_bounds__(256) void favor_kernel(
    const float* __restrict__ X0, const float* __restrict__ X1,
    const float* __restrict__ omega,
    float* __restrict__ P0, float* __restrict__ P1)
{
    __shared__ float om[DH * 32];
    __shared__ float xsb[8][DH];

    const float* X = blockIdx.y ? X1 : X0;
    float* Phi     = blockIdx.y ? P1 : P0;

    const int tid = threadIdx.x;
    for (int i = tid; i < DH * 32; i += 256) om[i] = omega[i];

    const int w    = tid >> 5;
    const int lane = tid & 31;
    const int gw   = blockIdx.x * 8 + w;
    const int token = gw >> 4;
    const int head  = gw & 15;

    const float scale = 0.35355339059327373f;   // 64^-0.25
    const size_t base = (size_t)token * D_MODEL + head * DH;

    float x0 = X[base + lane]      * scale;
    float x1 = X[base + 32 + lane] * scale;
    xsb[w][lane]      = x0;
    xsb[w][lane + 32] = x1;

    float hh = x0 * x0 + x1 * x1;
    #pragma unroll
    for (int o = 16; o; o >>= 1) hh += __shfl_xor_sync(0xffffffffu, hh, o);
    hh *= 0.5f;

    __syncthreads();

    float u = 0.f;
    #pragma unroll
    for (int d = 0; d < DH; d++)
        u = fmaf(xsb[w][d], om[d * 32 + lane], u);

    const float c = 0.125f;   // 64^-0.5
    Phi[base + lane]      = expf(u  - hh) * c;
    Phi[base + 32 + lane] = expf(-u - hh) * c;
}

// ============ chunked causal linear attention (token-parallel) ============
#define CST 68   // smem tile stride (words)

__device__ __forceinline__ void load_tile(
    float* dst, const float* __restrict__ src, size_t gbase, int tid)
{
    const int t = tid >> 2;
    const int qo = (tid & 3) * 16;
    const float* p = src + gbase + (size_t)t * D_MODEL + qo;
    float* d = dst + t * CST + qo;
    #pragma unroll
    for (int i = 0; i < 4; i++)
        *(float4*)(d + i * 4) = *(const float4*)(p + i * 4);
}

// Phase 1: S_c[m][d] = sum_t k[t][m] v[t][d] ; z_c[m] = sum_t k[t][m]
__global__ __launch_bounds__(256) void chunk_sums_kernel(
    const float* __restrict__ Kf, const float* __restrict__ V,
    float* __restrict__ gS, float* __restrict__ gZ)
{
    __shared__ float ks[64 * CST];
    __shared__ float vs[64 * CST];

    const int ch = blockIdx.x;
    const int bh = blockIdx.y;
    const int tid = threadIdx.x;
    const int b = bh >> 4, hd = bh & 15;
    const size_t gbase = (size_t)b * 1024 * D_MODEL + (size_t)(ch * CLEN) * D_MODEL + hd * DH;

    load_tile(ks, Kf, gbase, tid);
    load_tile(vs, V,  gbase, tid);
    __syncthreads();

    const int mg = (tid >> 4) * 4;
    const int dg = (tid & 15) * 4;

    float acc[4][4];
    float zz[4];
    #pragma unroll
    for (int e = 0; e < 4; e++) {
        zz[e] = 0.f;
        #pragma unroll
        for (int c = 0; c < 4; c++) acc[e][c] = 0.f;
    }

    #pragma unroll 4
    for (int t = 0; t < CLEN; t++) {
        float4 v4 = *(const float4*)(vs + t * CST + dg);
        #pragma unroll
        for (int e = 0; e < 4; e++) {
            const float kv = ks[t * CST + mg + e];
            zz[e] += kv;
            acc[e][0] = fmaf(kv, v4.x, acc[e][0]);
            acc[e][1] = fmaf(kv, v4.y, acc[e][1]);
            acc[e][2] = fmaf(kv, v4.z, acc[e][2]);
            acc[e][3] = fmaf(kv, v4.w, acc[e][3]);
        }
    }

    const size_t idx = (size_t)(bh * NCHUNK + ch);
    #pragma unroll
    for (int e = 0; e < 4; e++)
        *(float4*)(gS + idx * 4096 + (size_t)(mg + e) * 64 + dg) =
            make_float4(acc[e][0], acc[e][1], acc[e][2], acc[e][3]);
    if ((tid & 15) == 0) {
        #pragma unroll
        for (int e = 0; e < 4; e++) gZ[idx * 64 + mg + e] = zz[e];
    }
}

// Phase 2: exclusive prefix over 16 chunks — one thread per (bh, element).
__global__ __launch_bounds__(256) void chunk_prefix_kernel(
    float* __restrict__ gS, float* __restrict__ gZ)
{
    const int gid = blockIdx.x * 256 + threadIdx.x;   // 0 .. 131071
    const int bh = gid >> 12;
    const int e  = gid & 4095;

    const size_t base = (size_t)bh * (NCHUNK * 4096) + e;
    float vals[NCHUNK];
    #pragma unroll
    for (int ch = 0; ch < NCHUNK; ch++)
        vals[ch] = gS[base + (size_t)ch * 4096];

    float run = 0.f;
    #pragma unroll
    for (int ch = 0; ch < NCHUNK; ch++) {
        const float t = vals[ch];
        gS[base + (size_t)ch * 4096] = run;
        run += t;
    }

    if (e < 64) {
        const size_t zbase = (size_t)bh * (NCHUNK * 64) + e;
        float zv[NCHUNK];
        #pragma unroll
        for (int ch = 0; ch < NCHUNK; ch++)
            zv[ch] = gZ[zbase + ch * 64];
        float zr = 0.f;
        #pragma unroll
        for (int ch = 0; ch < NCHUNK; ch++) {
            const float t = zv[ch];
            gZ[zbase + ch * 64] = zr;
            zr += t;
        }
    }
}

// Phase 3: token-parallel intra-chunk attention.
__global__ __launch_bounds__(256) void chunk_attn_kernel(
    const float* __restrict__ Qf, const float* __restrict__ Kf,
    const float* __restrict__ V, const float* __restrict__ gS,
    const float* __restrict__ gZ, float* __restrict__ Out)
{
    extern __shared__ float smw[];
    float* qs = smw;                 // [i][m]
    float* kt = smw + 64 * CST;      // [m][j]
    float* vs = smw + 2 * 64 * CST;  // [j][d]
    float* Sp = smw + 3 * 64 * CST;  // [m][d]
    float* Am = smw + 4 * 64 * CST;  // [i][j]
    float* zp = smw + 5 * 64 * CST;  // [m]

    const int ch = blockIdx.x;
    const int bh = blockIdx.y;
    const int tid = threadIdx.x;
    const int b = bh >> 4, hd = bh & 15;
    const size_t gbase = (size_t)b * 1024 * D_MODEL + (size_t)(ch * CLEN) * D_MODEL + hd * DH;
    const size_t idx = (size_t)(bh * NCHUNK + ch);

    load_tile(qs, Qf, gbase, tid);
    load_tile(vs, V,  gbase, tid);
    {
        const int t = tid >> 2;
        const int qo = (tid & 3) * 16;
        const float* p = Kf + gbase + (size_t)t * D_MODEL + qo;
        #pragma unroll
        for (int i = 0; i < 16; i += 4) {
            float4 kv = *(const float4*)(p + i);
            kt[(qo + i + 0) * CST + t] = kv.x;
            kt[(qo + i + 1) * CST + t] = kv.y;
            kt[(qo + i + 2) * CST + t] = kv.z;
            kt[(qo + i + 3) * CST + t] = kv.w;
        }
    }
    {
        const int m = tid >> 2;
        const int qo = (tid & 3) * 16;
        const float* p = gS + idx * 4096 + (size_t)m * 64 + qo;
        float* dp = Sp + m * CST + qo;
        #pragma unroll
        for (int i = 0; i < 4; i++)
            *(float4*)(dp + i * 4) = *(const float4*)(p + i * 4);
    }
    if (tid < 64) zp[tid] = gZ[idx * 64 + tid];
    __syncthreads();

    const int ig = (tid >> 4) * 4;
    const int jg = (tid & 15) * 4;

    float a[4][4];
    float qz[4];
    #pragma unroll
    for (int e = 0; e < 4; e++) {
        qz[e] = 0.f;
        #pragma unroll
        for (int c = 0; c < 4; c++) a[e][c] = 0.f;
    }
    #pragma unroll 4
    for (int m = 0; m < DH; m++) {
        const float zv = zp[m];
        float4 k4 = *(const float4*)(kt + m * CST + jg);
        #pragma unroll
        for (int e = 0; e < 4; e++) {
            const float qv = qs[(ig + e) * CST + m];
            qz[e] = fmaf(qv, zv, qz[e]);
            a[e][0] = fmaf(qv, k4.x, a[e][0]);
            a[e][1] = fmaf(qv, k4.y, a[e][1]);
            a[e][2] = fmaf(qv, k4.z, a[e][2]);
            a[e][3] = fmaf(qv, k4.w, a[e][3]);
        }
    }
    float den[4];
    #pragma unroll
    for (int e = 0; e < 4; e++) {
        const int i = ig + e;
        #pragma unroll
        for (int c = 0; c < 4; c++)
            if (jg + c > i) a[e][c] = 0.f;
        float rs = a[e][0] + a[e][1] + a[e][2] + a[e][3];
        rs += __shfl_xor_sync(0xffffffffu, rs, 1);
        rs += __shfl_xor_sync(0xffffffffu, rs, 2);
        rs += __shfl_xor_sync(0xffffffffu, rs, 4);
        rs += __shfl_xor_sync(0xffffffffu, rs, 8);
        den[e] = qz[e] + rs + 1e-6f;
        *(float4*)(Am + i * CST + jg) = make_float4(a[e][0], a[e][1], a[e][2], a[e][3]);
    }
    __syncthreads();

    float acc[4][4];
    #pragma unroll
    for (int e = 0; e < 4; e++)
        #pragma unroll
        for (int c = 0; c < 4; c++) acc[e][c] = 0.f;

    #pragma unroll 4
    for (int m = 0; m < DH; m++) {
        float4 s4 = *(const float4*)(Sp + m * CST + jg);
        #pragma unroll
        for (int e = 0; e < 4; e++) {
            const float qv = qs[(ig + e) * CST + m];
            acc[e][0] = fmaf(qv, s4.x, acc[e][0]);
            acc[e][1] = fmaf(qv, s4.y, acc[e][1]);
            acc[e][2] = fmaf(qv, s4.z, acc[e][2]);
            acc[e][3] = fmaf(qv, s4.w, acc[e][3]);
        }
    }
    const int jmax = ig + 3;
    for (int j = 0; j <= jmax; j++) {
        float4 v4 = *(const float4*)(vs + j * CST + jg);
        #pragma unroll
        for (int e = 0; e < 4; e++) {
            const float av = Am[(ig + e) * CST + j];
            acc[e][0] = fmaf(av, v4.x, acc[e][0]);
            acc[e][1] = fmaf(av, v4.y, acc[e][1]);
            acc[e][2] = fmaf(av, v4.z, acc[e][2]);
            acc[e][3] = fmaf(av, v4.w, acc[e][3]);
        }
    }

    #pragma unroll
    for (int e = 0; e < 4; e++) {
        const float inv = 1.f / den[e];
        float* op = Out + gbase + (size_t)(ig + e) * D_MODEL + jg;
        *(float4*)op = make_float4(acc[e][0] * inv, acc[e][1] * inv,
                                   acc[e][2] * inv, acc[e][3] * inv);
    }
}
#define ATTN_SMEM ((5 * 64 * CST + 64) * 4)

// ---------------- LayerNorm(out = LN(a + r) * g + b) ----------------
__global__ __launch_bounds__(256) void ln_kernel(
    float* __restrict__ out, const float* __restrict__ a,
    const float* __restrict__ r, const float* __restrict__ gam,
    const float* __restrict__ bet)
{
    const int row = blockIdx.x;
    const int tid = threadIdx.x;
    const float* pa = a + (size_t)row * D_MODEL;
    const float* pr = r + (size_t)row * D_MODEL;

    float v[4];
    float s = 0.f, ss = 0.f;
    #pragma unroll
    for (int i = 0; i < 4; i++) {
        int idx = tid + i * 256;
        float t = pa[idx] + pr[idx];
        v[i] = t; s += t; ss = fmaf(t, t, ss);
    }

    __shared__ float red[18];
    #pragma unroll
    for (int o = 16; o; o >>= 1) {
        s  += __shfl_xor_sync(0xffffffffu, s,  o);
        ss += __shfl_xor_sync(0xffffffffu, ss, o);
    }
    const int w = tid >> 5, lane = tid & 31;
    __shared__ float rw[16];
    if (lane == 0) { rw[w] = s; rw[w + 8] = ss; }
    __syncthreads();
    if (tid == 0) {
        float S0 = 0.f, S1 = 0.f;
        #pragma unroll
        for (int i = 0; i < 8; i++) { S0 += rw[i]; S1 += rw[i + 8]; }
        red[16] = S0; red[17] = S1;
    }
    __syncthreads();

    const float mean = red[16] * (1.f / 1024.f);
    const float var  = red[17] * (1.f / 1024.f) - mean * mean;
    const float inv  = rsqrtf(var + 1e-5f);

    float* po = out + (size_t)row * D_MODEL;
    #pragma unroll
    for (int i = 0; i < 4; i++) {
        int idx = tid + i * 256;
        po[idx] = (v[i] - mean) * inv * gam[idx] + bet[idx];
    }
}

// ---------------- launch ----------------
extern "C" void kernel_launch(void* const* d_in, const int* in_sizes, int n_in,
                              void* d_out, int out_size)
{
    const float* x    = (const float*)d_in[0];
    const float* Wq   = (const float*)d_in[1];
    const float* bq   = (const float*)d_in[2];
    const float* Wk   = (const float*)d_in[3];
    const float* bk   = (const float*)d_in[4];
    const float* Wv   = (const float*)d_in[5];
    const float* bv   = (const float*)d_in[6];
    const float* Wo   = (const float*)d_in[7];
    const float* bo   = (const float*)d_in[8];
    const float* omg  = (const float*)d_in[9];
    const float* ln1g = (const float*)d_in[10];
    const float* ln1b = (const float*)d_in[11];
    const float* ln2g = (const float*)d_in[12];
    const float* ln2b = (const float*)d_in[13];
    const float* W1   = (const float*)d_in[14];
    const float* bf1  = (const float*)d_in[15];
    const float* W2   = (const float*)d_in[16];
    const float* bf2  = (const float*)d_in[17];
    float* out = (float*)d_out;

    float *cur, *q, *k, *v, *qf, *kf, *h, *ffn, *gS, *gZ;
    cudaGetSymbolAddress((void**)&cur, g_cur);
    cudaGetSymbolAddress((void**)&q,   g_q);
    cudaGetSymbolAddress((void**)&k,   g_k);
    cudaGetSymbolAddress((void**)&v,   g_v);
    cudaGetSymbolAddress((void**)&qf,  g_qf);
    cudaGetSymbolAddress((void**)&kf,  g_kf);
    cudaGetSymbolAddress((void**)&h,   g_h);
    cudaGetSymbolAddress((void**)&ffn, g_ffn);
    cudaGetSymbolAddress((void**)&gS,  g_S);
    cudaGetSymbolAddress((void**)&gZ,  g_Z);

    cudaFuncSetAttribute(mma_gemm, cudaFuncAttributeMaxDynamicSharedMemorySize, GEMM_SMEM);
    cudaFuncSetAttribute(chunk_attn_kernel, cudaFuncAttributeMaxDynamicSharedMemorySize, ATTN_SMEM);

    const dim3 gQKV(D_MODEL / 128, NTOK / 128, 3);
    const dim3 gD(D_MODEL / 128, NTOK / 128, 1);
    const dim3 gF(DFF_DIM / 128, NTOK / 128, 1);
    const dim3 gCh(NCHUNK, 32);
    const dim3 gFav(NTOK * NHEAD / 8, 2);
    const int  gPref = (32 * 4096) / 256;    // 512 blocks

    for (int l = 0; l < NLAYER; l++) {
        const size_t wDD  = (size_t)l * D_MODEL * D_MODEL;
        const size_t wDF  = (size_t)l * D_MODEL * DFF_DIM;
        const size_t bD   = (size_t)l * D_MODEL;
        const size_t bF   = (size_t)l * DFF_DIM;
        const size_t oOff = (size_t)l * DH * 32;
        const float* inA  = (l == 0) ? x : cur;

        mma_gemm<<<gQKV, 512, GEMM_SMEM>>>(inA,
            Wq + wDD, Wk + wDD, Wv + wDD,
            bq + bD, bk + bD, bv + bD,
            q, k, v, NTOK, D_MODEL, D_MODEL, 0);

        favor_kernel<<<gFav, 256>>>(q, k, omg + oOff, qf, kf);

        chunk_sums_kernel<<<gCh, 256>>>(kf, v, gS, gZ);
        chunk_prefix_kernel<<<gPref, 256>>>(gS, gZ);
        chunk_attn_kernel<<<gCh, 256, ATTN_SMEM>>>(qf, kf, v, gS, gZ, q);  // attn -> q

        mma_gemm<<<gD, 512, GEMM_SMEM>>>(q,
            Wo + wDD, Wo + wDD, Wo + wDD,
            bo + bD, bo + bD, bo + bD,
            k, k, k, NTOK, D_MODEL, D_MODEL, 0);
        ln_kernel<<<NTOK, 256>>>(h, inA, k, ln1g + bD, ln1b + bD);

        mma_gemm<<<gF, 512, GEMM_SMEM>>>(h,
            W1 + wDF, W1 + wDF, W1 + wDF,
            bf1 + bF, bf1 + bF, bf1 + bF,
            ffn, ffn, ffn, NTOK, DFF_DIM, D_MODEL, 1);
        mma_gemm<<<gD, 512, GEMM_SMEM>>>(ffn,
            W2 + wDF, W2 + wDF, W2 + wDF,
            bf2 + bD, bf2 + bD, bf2 + bD,
            v, v, v, NTOK, D_MODEL, DFF_DIM, 0);

        float* dst = (l == NLAYER - 1) ? out : cur;
        ln_kernel<<<NTOK, 256>>>(dst, h, v, ln2g + bD, ln2b + bD);
    }
}